// round 11
// baseline (speedup 1.0000x reference)
#include <cuda_runtime.h>
#include <cuda_bf16.h>
#include <math.h>
#include <cstdint>

#define SEQ   4096
#define DM    1024
#define NH    16
#define DK    64

// ---- bf16 hi/lo buffers ----
__device__ __nv_bfloat16 g_xh[SEQ * DM], g_xl[SEQ * DM];
__device__ __nv_bfloat16 g_ah[SEQ * DM], g_al[SEQ * DM];   // attention output
__device__ __nv_bfloat16 g_wqh[DM * DM], g_wql[DM * DM];
__device__ __nv_bfloat16 g_wkh[DM * DM], g_wkl[DM * DM];
__device__ __nv_bfloat16 g_wvh[DM * DM], g_wvl[DM * DM];
__device__ __nv_bfloat16 g_woh[DM * DM], g_wol[DM * DM];
// head-major [NH][SEQ][DK] Q/K/V hi/lo
__device__ __nv_bfloat16 g_qh[NH * SEQ * DK], g_ql[NH * SEQ * DK];
__device__ __nv_bfloat16 g_kh[NH * SEQ * DK], g_kl[NH * SEQ * DK];
__device__ __nv_bfloat16 g_vh[NH * SEQ * DK], g_vl[NH * SEQ * DK];

__device__ float g_rope_cos[SEQ * 32];
__device__ float g_rope_sin[SEQ * 32];

// ============================================================
// RoPE table (double trig, fp32 phase rounding like the reference)
// ============================================================
__global__ void rope_table_kernel() {
    int t = blockIdx.x * blockDim.x + threadIdx.x;
    int jj  = t & 31;
    int pos = t >> 5;
    if (pos >= SEQ) return;
    float invf = (float)pow(10000.0, -(double)jj / 32.0);
    float freq = (float)pos * invf;
    g_rope_cos[pos * 32 + jj] = (float)cos((double)freq);
    g_rope_sin[pos * 32 + jj] = (float)sin((double)freq);
}

// ============================================================
// fp32 -> (hi, lo) bf16 split
// ============================================================
__device__ __forceinline__ void split4(const float4 v,
                                       __nv_bfloat162* hi,
                                       __nv_bfloat162* lo, int i) {
    __nv_bfloat16 h0 = __float2bfloat16(v.x);
    __nv_bfloat16 h1 = __float2bfloat16(v.y);
    __nv_bfloat16 h2 = __float2bfloat16(v.z);
    __nv_bfloat16 h3 = __float2bfloat16(v.w);
    __nv_bfloat162 a, b, c, d;
    a.x = h0; a.y = h1;
    b.x = h2; b.y = h3;
    c.x = __float2bfloat16(v.x - __bfloat162float(h0));
    c.y = __float2bfloat16(v.y - __bfloat162float(h1));
    d.x = __float2bfloat16(v.z - __bfloat162float(h2));
    d.y = __float2bfloat16(v.w - __bfloat162float(h3));
    hi[2 * i + 0] = a;
    hi[2 * i + 1] = b;
    lo[2 * i + 0] = c;
    lo[2 * i + 1] = d;
}

__global__ void conv_split(const float4* __restrict__ src,
                           __nv_bfloat162* __restrict__ hi,
                           __nv_bfloat162* __restrict__ lo, int n4) {
    int i = blockIdx.x * blockDim.x + threadIdx.x;
    if (i >= n4) return;
    split4(src[i], hi, lo, i);
}

// batched: blockIdx.y selects (src, hi, lo) triple — wq/wk/wv in one launch
__global__ void conv_split3(const float4* __restrict__ s0,
                            const float4* __restrict__ s1,
                            const float4* __restrict__ s2,
                            __nv_bfloat162* __restrict__ h0, __nv_bfloat162* __restrict__ l0,
                            __nv_bfloat162* __restrict__ h1, __nv_bfloat162* __restrict__ l1,
                            __nv_bfloat162* __restrict__ h2, __nv_bfloat162* __restrict__ l2,
                            int n4) {
    int i = blockIdx.x * blockDim.x + threadIdx.x;
    if (i >= n4) return;
    const float4* src     = (blockIdx.y == 0) ? s0 : (blockIdx.y == 1) ? s1 : s2;
    __nv_bfloat162* hi    = (blockIdx.y == 0) ? h0 : (blockIdx.y == 1) ? h1 : h2;
    __nv_bfloat162* lo    = (blockIdx.y == 0) ? l0 : (blockIdx.y == 1) ? l1 : l2;
    split4(src[i], hi, lo, i);
}

// ============================================================
// warp-mma helpers
// ============================================================
__device__ __forceinline__ uint32_t s2u(const void* p) {
    uint32_t a;
    asm("{ .reg .u64 t; cvta.to.shared.u64 t, %1; cvt.u32.u64 %0, t; }"
        : "=r"(a) : "l"(p));
    return a;
}

__device__ __forceinline__ void mma16816(float* d, const uint32_t* a,
                                         uint32_t b0, uint32_t b1) {
    asm volatile(
        "mma.sync.aligned.m16n8k16.row.col.f32.bf16.bf16.f32 "
        "{%0,%1,%2,%3}, {%4,%5,%6,%7}, {%8,%9}, {%0,%1,%2,%3};"
        : "+f"(d[0]), "+f"(d[1]), "+f"(d[2]), "+f"(d[3])
        : "r"(a[0]), "r"(a[1]), "r"(a[2]), "r"(a[3]), "r"(b0), "r"(b1));
}

__device__ __forceinline__ void ldsm4(uint32_t* r, uint32_t addr) {
    asm volatile("ldmatrix.sync.aligned.m8n8.x4.shared.b16 {%0,%1,%2,%3}, [%4];"
                 : "=r"(r[0]), "=r"(r[1]), "=r"(r[2]), "=r"(r[3]) : "r"(addr));
}

__device__ __forceinline__ void ldsm4t(uint32_t* r, uint32_t addr) {
    asm volatile("ldmatrix.sync.aligned.m8n8.x4.trans.shared.b16 {%0,%1,%2,%3}, [%4];"
                 : "=r"(r[0]), "=r"(r[1]), "=r"(r[2]), "=r"(r[3]) : "r"(addr));
}

__device__ __forceinline__ uint32_t packbf2(float lo, float hi) {
    __nv_bfloat162 b = __float22bfloat162_rn(make_float2(lo, hi));
    return *(uint32_t*)&b;
}

// ============================================================
// bf16x3 GEMM via mma.sync (unchanged)
// ============================================================
#define KPAD      40
#define TILE_B    (128 * KPAD * 2)
#define STAGE_B   (4 * TILE_B)
#define GEMM_SMEM (2 * STAGE_B)

__device__ __forceinline__ void load_tile4(uint32_t st,
                                           const __nv_bfloat16* ah,
                                           const __nv_bfloat16* al,
                                           const __nv_bfloat16* bh,
                                           const __nv_bfloat16* bl, int tid) {
    #pragma unroll
    for (int i = 0; i < 2; i++) {
        int c   = tid + 256 * i;
        int row = c >> 2;
        int sg  = (c & 3) << 4;
        uint32_t soff = (uint32_t)row * (KPAD * 2) + (uint32_t)sg;
        size_t   goff = (size_t)row * (DM * 2) + sg;
        asm volatile("cp.async.cg.shared.global [%0], [%1], 16;"
                     :: "r"(st + 0 * TILE_B + soff), "l"((const char*)ah + goff) : "memory");
        asm volatile("cp.async.cg.shared.global [%0], [%1], 16;"
                     :: "r"(st + 1 * TILE_B + soff), "l"((const char*)al + goff) : "memory");
        asm volatile("cp.async.cg.shared.global [%0], [%1], 16;"
                     :: "r"(st + 2 * TILE_B + soff), "l"((const char*)bh + goff) : "memory");
        asm volatile("cp.async.cg.shared.global [%0], [%1], 16;"
                     :: "r"(st + 3 * TILE_B + soff), "l"((const char*)bl + goff) : "memory");
    }
}

__global__ void __launch_bounds__(256)
gemm_tc(const __nv_bfloat16* __restrict__ Ah, const __nv_bfloat16* __restrict__ Al,
        const __nv_bfloat16* __restrict__ B0h, const __nv_bfloat16* __restrict__ B0l,
        const __nv_bfloat16* __restrict__ B1h, const __nv_bfloat16* __restrict__ B1l,
        const __nv_bfloat16* __restrict__ B2h, const __nv_bfloat16* __restrict__ B2l,
        float* __restrict__ Dout,
        __nv_bfloat16* __restrict__ Oqh, __nv_bfloat16* __restrict__ Oql,
        __nv_bfloat16* __restrict__ Okh, __nv_bfloat16* __restrict__ Okl,
        __nv_bfloat16* __restrict__ Ovh, __nv_bfloat16* __restrict__ Ovl,
        int mode) {
    extern __shared__ char smraw[];
    const uint32_t sb = s2u(smraw);

    const int tid  = threadIdx.x;
    const int lane = tid & 31;
    const int wid  = tid >> 5;
    const int warp_m = (wid & 1) * 64;
    const int warp_n = (wid >> 1) * 32;

    const int ntile = blockIdx.x;
    const int which = ntile >> 3;
    const int nloc  = (ntile & 7) * 128;
    const int m0    = blockIdx.y * 128;

    const __nv_bfloat16* Bh = (which == 0) ? B0h : (which == 1) ? B1h : B2h;
    const __nv_bfloat16* Bl = (which == 0) ? B0l : (which == 1) ? B1l : B2l;

    const __nv_bfloat16* Abh = Ah + (size_t)m0 * DM;
    const __nv_bfloat16* Abl = Al + (size_t)m0 * DM;
    const __nv_bfloat16* Bbh = Bh + (size_t)nloc * DM;
    const __nv_bfloat16* Bbl = Bl + (size_t)nloc * DM;

    float acc[4][4][4];
    #pragma unroll
    for (int i = 0; i < 4; i++)
        #pragma unroll
        for (int j = 0; j < 4; j++)
            #pragma unroll
            for (int r = 0; r < 4; r++) acc[i][j][r] = 0.0f;

    const uint32_t a_off = (uint32_t)(lane & 15) * (KPAD * 2) + (uint32_t)(lane >> 4) * 16;
    const uint32_t b_off = (uint32_t)((lane & 7) + ((lane >> 3) & 1) * 8) * (KPAD * 2)
                         + (uint32_t)(lane >> 4) * 16;

    load_tile4(sb, Abh, Abl, Bbh, Bbl, tid);
    asm volatile("cp.async.commit_group;" ::: "memory");

    for (int kb = 0; kb < 32; kb++) {
        const uint32_t st = sb + (uint32_t)(kb & 1) * STAGE_B;
        if (kb + 1 < 32) {
            const int ko = (kb + 1) * 32;
            load_tile4(sb + (uint32_t)((kb + 1) & 1) * STAGE_B,
                       Abh + ko, Abl + ko, Bbh + ko, Bbl + ko, tid);
            asm volatile("cp.async.commit_group;" ::: "memory");
            asm volatile("cp.async.wait_group 1;" ::: "memory");
        } else {
            asm volatile("cp.async.wait_group 0;" ::: "memory");
        }
        __syncthreads();

        #pragma unroll
        for (int ks = 0; ks < 2; ks++) {
            const uint32_t k0b = (uint32_t)ks * 32;
            uint32_t ahf[4][4], alf[4][4], bh4[2][4], bl4[2][4];
            #pragma unroll
            for (int mi = 0; mi < 4; mi++) {
                uint32_t ra = (uint32_t)(warp_m + mi * 16) * (KPAD * 2) + k0b + a_off;
                ldsm4(ahf[mi], st + 0 * TILE_B + ra);
                ldsm4(alf[mi], st + 1 * TILE_B + ra);
            }
            #pragma unroll
            for (int n2 = 0; n2 < 2; n2++) {
                uint32_t rb = (uint32_t)(warp_n + n2 * 16) * (KPAD * 2) + k0b + b_off;
                ldsm4(bh4[n2], st + 2 * TILE_B + rb);
                ldsm4(bl4[n2], st + 3 * TILE_B + rb);
            }
            #pragma unroll
            for (int mi = 0; mi < 4; mi++)
                #pragma unroll
                for (int ni = 0; ni < 4; ni++) {
                    const int n2 = ni >> 1, hf = ni & 1;
                    mma16816(acc[mi][ni], ahf[mi], bh4[n2][hf], bh4[n2][hf + 2]);
                    mma16816(acc[mi][ni], ahf[mi], bl4[n2][hf], bl4[n2][hf + 2]);
                    mma16816(acc[mi][ni], alf[mi], bh4[n2][hf], bh4[n2][hf + 2]);
                }
        }
        __syncthreads();
    }

    const int rope = (mode == 1) && (which < 2);
    __nv_bfloat16* Wh = (which == 0) ? Oqh : (which == 1) ? Okh : Ovh;
    __nv_bfloat16* Wl = (which == 0) ? Oql : (which == 1) ? Okl : Ovl;

    #pragma unroll
    for (int mi = 0; mi < 4; mi++) {
        #pragma unroll
        for (int ni = 0; ni < 4; ni++) {
            const int r0  = m0 + warp_m + mi * 16 + (lane >> 2);
            const int col = nloc + warp_n + ni * 8 + (lane & 3) * 2;
            float c0 = acc[mi][ni][0], c1 = acc[mi][ni][1];
            float c2 = acc[mi][ni][2], c3 = acc[mi][ni][3];
            if (rope) {
                const int jj = (col & (DK - 1)) >> 1;
                float cs = g_rope_cos[r0 * 32 + jj];
                float sn = g_rope_sin[r0 * 32 + jj];
                float e = c0, o = c1;
                c0 = cs * e - sn * o;
                c1 = sn * e + cs * o;
                cs = g_rope_cos[(r0 + 8) * 32 + jj];
                sn = g_rope_sin[(r0 + 8) * 32 + jj];
                e = c2; o = c3;
                c2 = cs * e - sn * o;
                c3 = sn * e + cs * o;
            }
            if (mode == 0) {
                *(float2*)&Dout[(size_t)r0 * DM + col]       = make_float2(c0, c1);
                *(float2*)&Dout[(size_t)(r0 + 8) * DM + col] = make_float2(c2, c3);
            } else {
                const int head = col >> 6;
                const int d    = col & 63;
                const size_t p0 = ((size_t)head * SEQ + r0) * DK + d;
                const size_t p1 = ((size_t)head * SEQ + r0 + 8) * DK + d;
                __nv_bfloat162 h0 = __float22bfloat162_rn(make_float2(c0, c1));
                __nv_bfloat162 h1 = __float22bfloat162_rn(make_float2(c2, c3));
                __nv_bfloat162 l0 = __float22bfloat162_rn(make_float2(
                    c0 - __low2float(h0), c1 - __high2float(h0)));
                __nv_bfloat162 l1 = __float22bfloat162_rn(make_float2(
                    c2 - __low2float(h1), c3 - __high2float(h1)));
                *(__nv_bfloat162*)&Wh[p0] = h0;
                *(__nv_bfloat162*)&Wh[p1] = h1;
                *(__nv_bfloat162*)&Wl[p0] = l0;
                *(__nv_bfloat162*)&Wl[p1] = l1;
            }
        }
    }
}

// ============================================================
// Tensor-core causal flash attention v4.
// CTA = (head, 64-query block), 128 thr (4 warps x 16 rows).
// Q hi+lo fragments in registers; KV double buffer 73728 B.
// __launch_bounds__(128,3): regs capped 168 -> guaranteed 3 CTAs/SM.
// ============================================================
#define ASTR   72                       // halves per smem row
#define KVTILE (64 * ASTR * 2)          // 9216 B per 64x64 tile
#define ATT_SMEM (8 * KVTILE)           // 73728 B

__device__ __forceinline__ void aload64(uint32_t dst, const __nv_bfloat16* src,
                                        int tid) {
    const char* s = (const char*)src;
    #pragma unroll
    for (int i = 0; i < 4; i++) {
        int c   = tid + 128 * i;
        int row = c >> 3;
        int seg = (c & 7) << 4;
        asm volatile("cp.async.cg.shared.global [%0], [%1], 16;"
                     :: "r"(dst + (uint32_t)row * (ASTR * 2) + (uint32_t)seg),
                        "l"(s + (size_t)row * 128 + seg) : "memory");
    }
}

__global__ void __launch_bounds__(128, 3) attn_tc() {
    extern __shared__ char smraw[];
    const uint32_t kv0 = s2u(smraw);    // + stage*4*KVTILE: Kh,Kl,Vh,Vl

    const int tid  = threadIdx.x;
    const int lane = tid & 31;
    const int warp = tid >> 5;
    const int h    = blockIdx.y;
    const int qb   = gridDim.x - 1 - blockIdx.x;   // heavy-first
    const int q0   = qb * 64;

    const size_t hb = (size_t)h * SEQ * DK;

    const uint32_t qoff = (uint32_t)(warp * 16 + (lane & 15)) * (ASTR * 2)
                        + (uint32_t)(lane >> 4) * 16;
    const uint32_t krow = (uint32_t)((lane & 7) + ((lane >> 4) & 1) * 8);
    const uint32_t kcol = (uint32_t)((lane >> 3) & 1) * 16;
    const uint32_t vrow = (uint32_t)((lane & 7) + ((lane >> 3) & 1) * 8);
    const uint32_t vcol = (uint32_t)(lane >> 4) * 16;
    const float SCL = 0.125f * 1.44269504f;   // 1/sqrt(64) * log2(e)

    // ---- prologue: stage Q hi/lo through KV area -> registers ----
    aload64(kv0 + 0 * KVTILE, g_qh + hb + (size_t)q0 * DK, tid);
    aload64(kv0 + 1 * KVTILE, g_ql + hb + (size_t)q0 * DK, tid);
    asm volatile("cp.async.commit_group;" ::: "memory");
    asm volatile("cp.async.wait_group 0;" ::: "memory");
    __syncthreads();

    uint32_t qhf[4][4], qlf[4][4];
    #pragma unroll
    for (int ks = 0; ks < 4; ks++) {
        ldsm4(qhf[ks], kv0 + 0 * KVTILE + qoff + ks * 32);
        ldsm4(qlf[ks], kv0 + 1 * KVTILE + qoff + ks * 32);
    }
    __syncthreads();

    // KV block 0 into stage 0
    aload64(kv0 + 0 * KVTILE, g_kh + hb, tid);
    aload64(kv0 + 1 * KVTILE, g_kl + hb, tid);
    aload64(kv0 + 2 * KVTILE, g_vh + hb, tid);
    aload64(kv0 + 3 * KVTILE, g_vl + hb, tid);
    asm volatile("cp.async.commit_group;" ::: "memory");

    float o[8][4];
    #pragma unroll
    for (int j = 0; j < 8; j++)
        #pragma unroll
        for (int c = 0; c < 4; c++) o[j][c] = 0.0f;
    float m0 = -1e30f, m1 = -1e30f, l0 = 0.0f, l1 = 0.0f;

    for (int kb = 0; kb <= qb; kb++) {
        if (kb < qb) {
            const uint32_t nst = kv0 + (uint32_t)((kb + 1) & 1) * (4 * KVTILE);
            const size_t   gof = hb + (size_t)(kb + 1) * 64 * DK;
            aload64(nst + 0 * KVTILE, g_kh + gof, tid);
            aload64(nst + 1 * KVTILE, g_kl + gof, tid);
            aload64(nst + 2 * KVTILE, g_vh + gof, tid);
            aload64(nst + 3 * KVTILE, g_vl + gof, tid);
            asm volatile("cp.async.commit_group;" ::: "memory");
            asm volatile("cp.async.wait_group 1;" ::: "memory");
        } else {
            asm volatile("cp.async.wait_group 0;" ::: "memory");
        }
        __syncthreads();

        const uint32_t st   = kv0 + (uint32_t)(kb & 1) * (4 * KVTILE);
        const uint32_t kh_s = st, kl_s = st + KVTILE;
        const uint32_t vh_s = st + 2 * KVTILE, vl_s = st + 3 * KVTILE;

        // ---- S = Q K^T (bf16x3, Q frags resident) ----
        float sc[8][4];
        #pragma unroll
        for (int j = 0; j < 8; j++)
            #pragma unroll
            for (int c = 0; c < 4; c++) sc[j][c] = 0.0f;

        #pragma unroll
        for (int ks = 0; ks < 4; ks++) {
            #pragma unroll
            for (int nb = 0; nb < 4; nb++) {
                uint32_t ra = (uint32_t)(nb * 16 + krow) * (ASTR * 2) + kcol + ks * 32;
                uint32_t bkh[4], bkl[4];
                ldsm4(bkh, kh_s + ra);
                ldsm4(bkl, kl_s + ra);
                mma16816(sc[2 * nb],     qhf[ks], bkh[0], bkh[1]);
                mma16816(sc[2 * nb],     qhf[ks], bkl[0], bkl[1]);
                mma16816(sc[2 * nb],     qlf[ks], bkh[0], bkh[1]);
                mma16816(sc[2 * nb + 1], qhf[ks], bkh[2], bkh[3]);
                mma16816(sc[2 * nb + 1], qhf[ks], bkl[2], bkl[3]);
                mma16816(sc[2 * nb + 1], qlf[ks], bkh[2], bkh[3]);
            }
        }

        // ---- scale (pre-multiplied by log2 e) + causal mask ----
        #pragma unroll
        for (int j = 0; j < 8; j++)
            #pragma unroll
            for (int c = 0; c < 4; c++) sc[j][c] *= SCL;
        if (kb == qb) {
            const int r0 = q0 + warp * 16 + (lane >> 2);
            #pragma unroll
            for (int j = 0; j < 8; j++)
                #pragma unroll
                for (int c = 0; c < 4; c++) {
                    const int col = kb * 64 + j * 8 + (lane & 3) * 2 + (c & 1);
                    const int row = r0 + (c >> 1) * 8;
                    if (col > row) sc[j][c] = -1e30f;
                }
        }

        // ---- online softmax (base-2) ----
        float mx0 = -1e30f, mx1 = -1e30f;
        #pragma unroll
        for (int j = 0; j < 8; j++) {
            mx0 = fmaxf(mx0, fmaxf(sc[j][0], sc[j][1]));
            mx1 = fmaxf(mx1, fmaxf(sc[j][2], sc[j][3]));
        }
        mx0 = fmaxf(mx0, __shfl_xor_sync(0xffffffffu, mx0, 1));
        mx0 = fmaxf(mx0, __shfl_xor_sync(0xffffffffu, mx0, 2));
        mx1 = fmaxf(mx1, __shfl_xor_sync(0xffffffffu, mx1, 1));
        mx1 = fmaxf(mx1, __shfl_xor_sync(0xffffffffu, mx1, 2));
        const float mn0 = fmaxf(m0, mx0), mn1 = fmaxf(m1, mx1);
        const float a0  = exp2f(m0 - mn0);
        const float a1  = exp2f(m1 - mn1);
        m0 = mn0; m1 = mn1;

        float s0 = 0.0f, s1 = 0.0f;
        #pragma unroll
        for (int j = 0; j < 8; j++) {
            sc[j][0] = exp2f(sc[j][0] - mn0);
            sc[j][1] = exp2f(sc[j][1] - mn0);
            sc[j][2] = exp2f(sc[j][2] - mn1);
            sc[j][3] = exp2f(sc[j][3] - mn1);
            s0 += sc[j][0] + sc[j][1];
            s1 += sc[j][2] + sc[j][3];
        }
        s0 += __shfl_xor_sync(0xffffffffu, s0, 1);
        s0 += __shfl_xor_sync(0xffffffffu, s0, 2);
        s1 += __shfl_xor_sync(0xffffffffu, s1, 1);
        s1 += __shfl_xor_sync(0xffffffffu, s1, 2);
        l0 = l0 * a0 + s0;
        l1 = l1 * a1 + s1;
        #pragma unroll
        for (int j = 0; j < 8; j++) {
            o[j][0] *= a0; o[j][1] *= a0;
            o[j][2] *= a1; o[j][3] *= a1;
        }

        // ---- O += P V (bf16x3, P repacked C->A in registers) ----
        #pragma unroll
        for (int j = 0; j < 4; j++) {
            const int t0 = 2 * j, t1 = 2 * j + 1;
            uint32_t ph[4], pl[4];
            ph[0] = packbf2(sc[t0][0], sc[t0][1]);
            ph[1] = packbf2(sc[t0][2], sc[t0][3]);
            ph[2] = packbf2(sc[t1][0], sc[t1][1]);
            ph[3] = packbf2(sc[t1][2], sc[t1][3]);
            {
                __nv_bfloat162 b0 = *(__nv_bfloat162*)&ph[0];
                __nv_bfloat162 b1 = *(__nv_bfloat162*)&ph[1];
                __nv_bfloat162 b2 = *(__nv_bfloat162*)&ph[2];
                __nv_bfloat162 b3 = *(__nv_bfloat162*)&ph[3];
                pl[0] = packbf2(sc[t0][0] - __low2float(b0), sc[t0][1] - __high2float(b0));
                pl[1] = packbf2(sc[t0][2] - __low2float(b1), sc[t0][3] - __high2float(b1));
                pl[2] = packbf2(sc[t1][0] - __low2float(b2), sc[t1][1] - __high2float(b2));
                pl[3] = packbf2(sc[t1][2] - __low2float(b3), sc[t1][3] - __high2float(b3));
            }
            #pragma unroll
            for (int nb = 0; nb < 4; nb++) {
                uint32_t ra = (uint32_t)(j * 16 + vrow) * (ASTR * 2) + vcol + nb * 32;
                uint32_t bvh[4], bvl[4];
                ldsm4t(bvh, vh_s + ra);
                ldsm4t(bvl, vl_s + ra);
                mma16816(o[2 * nb],     ph, bvh[0], bvh[1]);
                mma16816(o[2 * nb],     ph, bvl[0], bvl[1]);
                mma16816(o[2 * nb],     pl, bvh[0], bvh[1]);
                mma16816(o[2 * nb + 1], ph, bvh[2], bvh[3]);
                mma16816(o[2 * nb + 1], ph, bvl[2], bvl[3]);
                mma16816(o[2 * nb + 1], pl, bvh[2], bvh[3]);
            }
        }
        __syncthreads();
    }

    // ---- normalize + write bf16 hi/lo (row-major [SEQ][DM]) ----
    const float inv0 = 1.0f / l0, inv1 = 1.0f / l1;
    const int r  = q0 + warp * 16 + (lane >> 2);
    const int cb = h * 64 + (lane & 3) * 2;
    #pragma unroll
    for (int j = 0; j < 8; j++) {
        const int col = cb + j * 8;
        float f0 = o[j][0] * inv0, f1 = o[j][1] * inv0;
        float f2 = o[j][2] * inv1, f3 = o[j][3] * inv1;
        __nv_bfloat162 h0 = __float22bfloat162_rn(make_float2(f0, f1));
        __nv_bfloat162 h1 = __float22bfloat162_rn(make_float2(f2, f3));
        __nv_bfloat162 l0v = __float22bfloat162_rn(make_float2(
            f0 - __low2float(h0), f1 - __high2float(h0)));
        __nv_bfloat162 l1v = __float22bfloat162_rn(make_float2(
            f2 - __low2float(h1), f3 - __high2float(h1)));
        *(__nv_bfloat162*)&g_ah[(size_t)r * DM + col]       = h0;
        *(__nv_bfloat162*)&g_al[(size_t)r * DM + col]       = l0v;
        *(__nv_bfloat162*)&g_ah[(size_t)(r + 8) * DM + col] = h1;
        *(__nv_bfloat162*)&g_al[(size_t)(r + 8) * DM + col] = l1v;
    }
}

// ============================================================
// launch — attn_tc is the 6th launch so ncu (-s 5 -c 1) captures it
// ============================================================
extern "C" void kernel_launch(void* const* d_in, const int* in_sizes, int n_in,
                              void* d_out, int out_size) {
    const float* x  = (const float*)d_in[0];
    const float* wq = (const float*)d_in[1];
    const float* wk = (const float*)d_in[2];
    const float* wv = (const float*)d_in[3];
    const float* wo = (const float*)d_in[4];
    float* out = (float*)d_out;

    __nv_bfloat16 *xh, *xl, *ah, *al;
    __nv_bfloat16 *wqh, *wql, *wkh, *wkl, *wvh, *wvl, *woh, *wol;
    __nv_bfloat16 *qh, *ql, *kh, *kl, *vh, *vl;
    cudaGetSymbolAddress((void**)&xh,  g_xh);
    cudaGetSymbolAddress((void**)&xl,  g_xl);
    cudaGetSymbolAddress((void**)&ah,  g_ah);
    cudaGetSymbolAddress((void**)&al,  g_al);
    cudaGetSymbolAddress((void**)&wqh, g_wqh);
    cudaGetSymbolAddress((void**)&wql, g_wql);
    cudaGetSymbolAddress((void**)&wkh, g_wkh);
    cudaGetSymbolAddress((void**)&wkl, g_wkl);
    cudaGetSymbolAddress((void**)&wvh, g_wvh);
    cudaGetSymbolAddress((void**)&wvl, g_wvl);
    cudaGetSymbolAddress((void**)&woh, g_woh);
    cudaGetSymbolAddress((void**)&wol, g_wol);
    cudaGetSymbolAddress((void**)&qh,  g_qh);
    cudaGetSymbolAddress((void**)&ql,  g_ql);
    cudaGetSymbolAddress((void**)&kh,  g_kh);
    cudaGetSymbolAddress((void**)&kl,  g_kl);
    cudaGetSymbolAddress((void**)&vh,  g_vh);
    cudaGetSymbolAddress((void**)&vl,  g_vl);

    cudaFuncSetAttribute(gemm_tc,
                         cudaFuncAttributeMaxDynamicSharedMemorySize, GEMM_SMEM);
    cudaFuncSetAttribute(attn_tc,
                         cudaFuncAttributeMaxDynamicSharedMemorySize, ATT_SMEM);
    cudaFuncSetAttribute(attn_tc,
                         cudaFuncAttributePreferredSharedMemoryCarveout, 100);

    const int nx4 = SEQ * DM / 4;
    const int nw4 = DM * DM / 4;

    // 1: rope table
    rope_table_kernel<<<(SEQ * 32) / 256, 256>>>();
    // 2: x split
    conv_split<<<(nx4 + 255) / 256, 256>>>((const float4*)x,
                                           (__nv_bfloat162*)xh, (__nv_bfloat162*)xl, nx4);
    // 3: wq/wk/wv split (batched)
    conv_split3<<<dim3((nw4 + 255) / 256, 3), 256>>>(
        (const float4*)wq, (const float4*)wk, (const float4*)wv,
        (__nv_bfloat162*)wqh, (__nv_bfloat162*)wql,
        (__nv_bfloat162*)wkh, (__nv_bfloat162*)wkl,
        (__nv_bfloat162*)wvh, (__nv_bfloat162*)wvl, nw4);
    // 4: wo split
    conv_split<<<(nw4 + 255) / 256, 256>>>((const float4*)wo,
                                           (__nv_bfloat162*)woh, (__nv_bfloat162*)wol, nw4);
    // 5: QKV gemm (RoPE fused, head-major hi/lo out)
    gemm_tc<<<dim3(24, 32), 256, GEMM_SMEM>>>(xh, xl,
                                              wqh, wql, wkh, wkl, wvh, wvl,
                                              nullptr,
                                              qh, ql, kh, kl, vh, vl, 1);
    // 6: attention  <-- ncu -s 5 -c 1 captures this launch
    attn_tc<<<dim3(SEQ / 64, NH), 128, ATT_SMEM>>>();
    // 7: Wo gemm, fp32 out
    gemm_tc<<<dim3(8, 32), 256, GEMM_SMEM>>>(ah, al,
                                             woh, wol, woh, wol, woh, wol,
                                             out,
                                             nullptr, nullptr, nullptr,
                                             nullptr, nullptr, nullptr, 0);
}

// round 12
// speedup vs baseline: 1.0491x; 1.0491x over previous
#include <cuda_runtime.h>
#include <cuda_bf16.h>
#include <math.h>
#include <cstdint>

#define SEQ   4096
#define DM    1024
#define NH    16
#define DK    64

// ---- bf16 hi/lo buffers ----
__device__ __nv_bfloat16 g_xh[SEQ * DM], g_xl[SEQ * DM];
__device__ __nv_bfloat16 g_ah[SEQ * DM], g_al[SEQ * DM];   // attention output
__device__ __nv_bfloat16 g_wqh[DM * DM], g_wql[DM * DM];
__device__ __nv_bfloat16 g_wkh[DM * DM], g_wkl[DM * DM];
__device__ __nv_bfloat16 g_wvh[DM * DM], g_wvl[DM * DM];
__device__ __nv_bfloat16 g_woh[DM * DM], g_wol[DM * DM];
// head-major [NH][SEQ][DK] Q/K/V hi/lo
__device__ __nv_bfloat16 g_qh[NH * SEQ * DK], g_ql[NH * SEQ * DK];
__device__ __nv_bfloat16 g_kh[NH * SEQ * DK], g_kl[NH * SEQ * DK];
__device__ __nv_bfloat16 g_vh[NH * SEQ * DK], g_vl[NH * SEQ * DK];

__device__ float g_rope_cos[SEQ * 32];
__device__ float g_rope_sin[SEQ * 32];

// ============================================================
// RoPE table (double trig, fp32 phase rounding like the reference)
// ============================================================
__global__ void rope_table_kernel() {
    int t = blockIdx.x * blockDim.x + threadIdx.x;
    int jj  = t & 31;
    int pos = t >> 5;
    if (pos >= SEQ) return;
    float invf = (float)pow(10000.0, -(double)jj / 32.0);
    float freq = (float)pos * invf;
    g_rope_cos[pos * 32 + jj] = (float)cos((double)freq);
    g_rope_sin[pos * 32 + jj] = (float)sin((double)freq);
}

// ============================================================
// fp32 -> (hi, lo) bf16 split
// ============================================================
__device__ __forceinline__ void split4(const float4 v,
                                       __nv_bfloat162* hi,
                                       __nv_bfloat162* lo, int i) {
    __nv_bfloat16 h0 = __float2bfloat16(v.x);
    __nv_bfloat16 h1 = __float2bfloat16(v.y);
    __nv_bfloat16 h2 = __float2bfloat16(v.z);
    __nv_bfloat16 h3 = __float2bfloat16(v.w);
    __nv_bfloat162 a, b, c, d;
    a.x = h0; a.y = h1;
    b.x = h2; b.y = h3;
    c.x = __float2bfloat16(v.x - __bfloat162float(h0));
    c.y = __float2bfloat16(v.y - __bfloat162float(h1));
    d.x = __float2bfloat16(v.z - __bfloat162float(h2));
    d.y = __float2bfloat16(v.w - __bfloat162float(h3));
    hi[2 * i + 0] = a;
    hi[2 * i + 1] = b;
    lo[2 * i + 0] = c;
    lo[2 * i + 1] = d;
}

__global__ void conv_split(const float4* __restrict__ src,
                           __nv_bfloat162* __restrict__ hi,
                           __nv_bfloat162* __restrict__ lo, int n4) {
    int i = blockIdx.x * blockDim.x + threadIdx.x;
    if (i >= n4) return;
    split4(src[i], hi, lo, i);
}

// batched: blockIdx.y selects (src, hi, lo) triple — wq/wk/wv in one launch
__global__ void conv_split3(const float4* __restrict__ s0,
                            const float4* __restrict__ s1,
                            const float4* __restrict__ s2,
                            __nv_bfloat162* __restrict__ h0, __nv_bfloat162* __restrict__ l0,
                            __nv_bfloat162* __restrict__ h1, __nv_bfloat162* __restrict__ l1,
                            __nv_bfloat162* __restrict__ h2, __nv_bfloat162* __restrict__ l2,
                            int n4) {
    int i = blockIdx.x * blockDim.x + threadIdx.x;
    if (i >= n4) return;
    const float4* src  = (blockIdx.y == 0) ? s0 : (blockIdx.y == 1) ? s1 : s2;
    __nv_bfloat162* hi = (blockIdx.y == 0) ? h0 : (blockIdx.y == 1) ? h1 : h2;
    __nv_bfloat162* lo = (blockIdx.y == 0) ? l0 : (blockIdx.y == 1) ? l1 : l2;
    split4(src[i], hi, lo, i);
}

// ============================================================
// warp-mma helpers
// ============================================================
__device__ __forceinline__ uint32_t s2u(const void* p) {
    uint32_t a;
    asm("{ .reg .u64 t; cvta.to.shared.u64 t, %1; cvt.u32.u64 %0, t; }"
        : "=r"(a) : "l"(p));
    return a;
}

__device__ __forceinline__ void mma16816(float* d, const uint32_t* a,
                                         const uint32_t* b) {
    asm volatile(
        "mma.sync.aligned.m16n8k16.row.col.f32.bf16.bf16.f32 "
        "{%0,%1,%2,%3}, {%4,%5,%6,%7}, {%8,%9}, {%0,%1,%2,%3};"
        : "+f"(d[0]), "+f"(d[1]), "+f"(d[2]), "+f"(d[3])
        : "r"(a[0]), "r"(a[1]), "r"(a[2]), "r"(a[3]), "r"(b[0]), "r"(b[1]));
}

__device__ __forceinline__ void ldsm4(uint32_t* r, uint32_t addr) {
    asm volatile("ldmatrix.sync.aligned.m8n8.x4.shared.b16 {%0,%1,%2,%3}, [%4];"
                 : "=r"(r[0]), "=r"(r[1]), "=r"(r[2]), "=r"(r[3]) : "r"(addr));
}

__device__ __forceinline__ void ldsm4t(uint32_t* r, uint32_t addr) {
    asm volatile("ldmatrix.sync.aligned.m8n8.x4.trans.shared.b16 {%0,%1,%2,%3}, [%4];"
                 : "=r"(r[0]), "=r"(r[1]), "=r"(r[2]), "=r"(r[3]) : "r"(addr));
}

__device__ __forceinline__ void ldsm2(uint32_t* r, uint32_t addr) {
    asm volatile("ldmatrix.sync.aligned.m8n8.x2.shared.b16 {%0,%1}, [%2];"
                 : "=r"(r[0]), "=r"(r[1]) : "r"(addr));
}

__device__ __forceinline__ uint32_t packbf2(float lo, float hi) {
    __nv_bfloat162 b = __float22bfloat162_rn(make_float2(lo, hi));
    return *(uint32_t*)&b;
}

// ============================================================
// bf16x3 GEMM via mma.sync (ROUND-4 VERSION, ldsm2 B-frags):
// D[m,n] = sum_k A[m,k] * B[n,k]
// CTA 128x128, BK=32, 256 thr (8 warps, 64x32 warp tiles).
// mode 0: fp32 output. mode 1: QKV epilogue (RoPE + hi/lo head-major).
// ============================================================
#define KPAD      40
#define TILE_B    (128 * KPAD * 2)
#define STAGE_B   (4 * TILE_B)
#define GEMM_SMEM (2 * STAGE_B)

__device__ __forceinline__ void load_tile4(uint32_t st,
                                           const __nv_bfloat16* ah,
                                           const __nv_bfloat16* al,
                                           const __nv_bfloat16* bh,
                                           const __nv_bfloat16* bl, int tid) {
    #pragma unroll
    for (int i = 0; i < 2; i++) {
        int c   = tid + 256 * i;
        int row = c >> 2;
        int sg  = (c & 3) << 4;
        uint32_t soff = (uint32_t)row * (KPAD * 2) + (uint32_t)sg;
        size_t   goff = (size_t)row * (DM * 2) + sg;
        asm volatile("cp.async.cg.shared.global [%0], [%1], 16;"
                     :: "r"(st + 0 * TILE_B + soff), "l"((const char*)ah + goff) : "memory");
        asm volatile("cp.async.cg.shared.global [%0], [%1], 16;"
                     :: "r"(st + 1 * TILE_B + soff), "l"((const char*)al + goff) : "memory");
        asm volatile("cp.async.cg.shared.global [%0], [%1], 16;"
                     :: "r"(st + 2 * TILE_B + soff), "l"((const char*)bh + goff) : "memory");
        asm volatile("cp.async.cg.shared.global [%0], [%1], 16;"
                     :: "r"(st + 3 * TILE_B + soff), "l"((const char*)bl + goff) : "memory");
    }
}

__global__ void __launch_bounds__(256)
gemm_tc(const __nv_bfloat16* __restrict__ Ah, const __nv_bfloat16* __restrict__ Al,
        const __nv_bfloat16* __restrict__ B0h, const __nv_bfloat16* __restrict__ B0l,
        const __nv_bfloat16* __restrict__ B1h, const __nv_bfloat16* __restrict__ B1l,
        const __nv_bfloat16* __restrict__ B2h, const __nv_bfloat16* __restrict__ B2l,
        float* __restrict__ Dout,
        __nv_bfloat16* __restrict__ Oqh, __nv_bfloat16* __restrict__ Oql,
        __nv_bfloat16* __restrict__ Okh, __nv_bfloat16* __restrict__ Okl,
        __nv_bfloat16* __restrict__ Ovh, __nv_bfloat16* __restrict__ Ovl,
        int mode) {
    extern __shared__ char smraw[];
    const uint32_t sb = s2u(smraw);

    const int tid  = threadIdx.x;
    const int lane = tid & 31;
    const int wid  = tid >> 5;
    const int warp_m = (wid & 1) * 64;
    const int warp_n = (wid >> 1) * 32;

    const int ntile = blockIdx.x;
    const int which = ntile >> 3;
    const int nloc  = (ntile & 7) * 128;
    const int m0    = blockIdx.y * 128;

    const __nv_bfloat16* Bh = (which == 0) ? B0h : (which == 1) ? B1h : B2h;
    const __nv_bfloat16* Bl = (which == 0) ? B0l : (which == 1) ? B1l : B2l;

    const __nv_bfloat16* Abh = Ah + (size_t)m0 * DM;
    const __nv_bfloat16* Abl = Al + (size_t)m0 * DM;
    const __nv_bfloat16* Bbh = Bh + (size_t)nloc * DM;
    const __nv_bfloat16* Bbl = Bl + (size_t)nloc * DM;

    float acc[4][4][4];
    #pragma unroll
    for (int i = 0; i < 4; i++)
        #pragma unroll
        for (int j = 0; j < 4; j++)
            #pragma unroll
            for (int r = 0; r < 4; r++) acc[i][j][r] = 0.0f;

    const uint32_t a_off = (uint32_t)(lane & 15) * (KPAD * 2) + (uint32_t)(lane >> 4) * 16;
    const int bl16 = lane & 15;
    const uint32_t b_off = (uint32_t)(bl16 & 7) * (KPAD * 2) + (uint32_t)(bl16 >> 3) * 16;

    load_tile4(sb, Abh, Abl, Bbh, Bbl, tid);
    asm volatile("cp.async.commit_group;" ::: "memory");

    for (int kb = 0; kb < 32; kb++) {
        const uint32_t st = sb + (uint32_t)(kb & 1) * STAGE_B;
        if (kb + 1 < 32) {
            const int ko = (kb + 1) * 32;
            load_tile4(sb + (uint32_t)((kb + 1) & 1) * STAGE_B,
                       Abh + ko, Abl + ko, Bbh + ko, Bbl + ko, tid);
            asm volatile("cp.async.commit_group;" ::: "memory");
            asm volatile("cp.async.wait_group 1;" ::: "memory");
        } else {
            asm volatile("cp.async.wait_group 0;" ::: "memory");
        }
        __syncthreads();

        #pragma unroll
        for (int ks = 0; ks < 2; ks++) {
            const uint32_t k0b = (uint32_t)ks * 32;
            uint32_t ahf[4][4], alf[4][4], bhf[4][2], blf[4][2];
            #pragma unroll
            for (int mi = 0; mi < 4; mi++) {
                uint32_t ra = (uint32_t)(warp_m + mi * 16) * (KPAD * 2) + k0b + a_off;
                ldsm4(ahf[mi], st + 0 * TILE_B + ra);
                ldsm4(alf[mi], st + 1 * TILE_B + ra);
            }
            #pragma unroll
            for (int ni = 0; ni < 4; ni++) {
                uint32_t rb = (uint32_t)(warp_n + ni * 8) * (KPAD * 2) + k0b + b_off;
                ldsm2(bhf[ni], st + 2 * TILE_B + rb);
                ldsm2(blf[ni], st + 3 * TILE_B + rb);
            }
            #pragma unroll
            for (int mi = 0; mi < 4; mi++)
                #pragma unroll
                for (int ni = 0; ni < 4; ni++) {
                    mma16816(acc[mi][ni], ahf[mi], bhf[ni]);
                    mma16816(acc[mi][ni], ahf[mi], blf[ni]);
                    mma16816(acc[mi][ni], alf[mi], bhf[ni]);
                }
        }
        __syncthreads();
    }

    const int rope = (mode == 1) && (which < 2);
    __nv_bfloat16* Wh = (which == 0) ? Oqh : (which == 1) ? Okh : Ovh;
    __nv_bfloat16* Wl = (which == 0) ? Oql : (which == 1) ? Okl : Ovl;

    #pragma unroll
    for (int mi = 0; mi < 4; mi++) {
        #pragma unroll
        for (int ni = 0; ni < 4; ni++) {
            const int r0  = m0 + warp_m + mi * 16 + (lane >> 2);
            const int col = nloc + warp_n + ni * 8 + (lane & 3) * 2;
            float c0 = acc[mi][ni][0], c1 = acc[mi][ni][1];
            float c2 = acc[mi][ni][2], c3 = acc[mi][ni][3];
            if (rope) {
                const int jj = (col & (DK - 1)) >> 1;
                float cs = g_rope_cos[r0 * 32 + jj];
                float sn = g_rope_sin[r0 * 32 + jj];
                float e = c0, o = c1;
                c0 = cs * e - sn * o;
                c1 = sn * e + cs * o;
                cs = g_rope_cos[(r0 + 8) * 32 + jj];
                sn = g_rope_sin[(r0 + 8) * 32 + jj];
                e = c2; o = c3;
                c2 = cs * e - sn * o;
                c3 = sn * e + cs * o;
            }
            if (mode == 0) {
                *(float2*)&Dout[(size_t)r0 * DM + col]       = make_float2(c0, c1);
                *(float2*)&Dout[(size_t)(r0 + 8) * DM + col] = make_float2(c2, c3);
            } else {
                const int head = col >> 6;
                const int d    = col & 63;
                const size_t p0 = ((size_t)head * SEQ + r0) * DK + d;
                const size_t p1 = ((size_t)head * SEQ + r0 + 8) * DK + d;
                __nv_bfloat162 h0 = __float22bfloat162_rn(make_float2(c0, c1));
                __nv_bfloat162 h1 = __float22bfloat162_rn(make_float2(c2, c3));
                __nv_bfloat162 l0 = __float22bfloat162_rn(make_float2(
                    c0 - __low2float(h0), c1 - __high2float(h0)));
                __nv_bfloat162 l1 = __float22bfloat162_rn(make_float2(
                    c2 - __low2float(h1), c3 - __high2float(h1)));
                *(__nv_bfloat162*)&Wh[p0] = h0;
                *(__nv_bfloat162*)&Wh[p1] = h1;
                *(__nv_bfloat162*)&Wl[p0] = l0;
                *(__nv_bfloat162*)&Wl[p1] = l1;
            }
        }
    }
}

// ============================================================
// Tensor-core causal flash attention (ROUND-4 SHAPE + deferred sum).
// CTA = (head, 64-query block). 128 thr, 4 warps x 16 rows.
// Q hi/lo in smem; K/V 64-key blocks double-buffered.
// Row-sum l kept as per-thread partial; reduced once at the end.
// ============================================================
#define ASTR  72                       // halves per smem row
#define ATILE (64 * ASTR * 2)          // 9216 B per 64x64 tile
#define ATT_SMEM (10 * ATILE)          // Qh,Ql + 2 stages x (Kh,Kl,Vh,Vl)

__device__ __forceinline__ void aload(uint32_t dst, const __nv_bfloat16* src,
                                      int tid) {
    const char* s = (const char*)src;
    #pragma unroll
    for (int i = 0; i < 4; i++) {
        int c   = tid + 128 * i;
        int row = c >> 3;
        int seg = (c & 7) << 4;
        asm volatile("cp.async.cg.shared.global [%0], [%1], 16;"
                     :: "r"(dst + (uint32_t)row * (ASTR * 2) + (uint32_t)seg),
                        "l"(s + (size_t)row * 128 + seg) : "memory");
    }
}

__global__ void __launch_bounds__(128) attn_tc() {
    extern __shared__ char smraw[];
    const uint32_t sb   = s2u(smraw);
    const uint32_t qh_s = sb;
    const uint32_t ql_s = sb + ATILE;
    const uint32_t kv0  = sb + 2 * ATILE;   // + stage*4*ATILE: Kh,Kl,Vh,Vl

    const int tid  = threadIdx.x;
    const int lane = tid & 31;
    const int warp = tid >> 5;
    const int h    = blockIdx.y;
    const int qb   = gridDim.x - 1 - blockIdx.x;   // heavy-first
    const int q0   = qb * 64;

    const size_t hb = (size_t)h * SEQ * DK;

    // Q tile + KV block 0
    aload(qh_s, g_qh + hb + (size_t)q0 * DK, tid);
    aload(ql_s, g_ql + hb + (size_t)q0 * DK, tid);
    aload(kv0 + 0 * ATILE, g_kh + hb, tid);
    aload(kv0 + 1 * ATILE, g_kl + hb, tid);
    aload(kv0 + 2 * ATILE, g_vh + hb, tid);
    aload(kv0 + 3 * ATILE, g_vl + hb, tid);
    asm volatile("cp.async.commit_group;" ::: "memory");

    float o[8][4];
    #pragma unroll
    for (int j = 0; j < 8; j++)
        #pragma unroll
        for (int c = 0; c < 4; c++) o[j][c] = 0.0f;
    float m0 = -1e30f, m1 = -1e30f;
    float lp0 = 0.0f, lp1 = 0.0f;      // per-thread partial row sums

    const uint32_t qoff = (uint32_t)(warp * 16 + (lane & 15)) * (ASTR * 2)
                        + (uint32_t)(lane >> 4) * 16;
    const uint32_t krow = (uint32_t)((lane & 7) + ((lane >> 4) & 1) * 8);
    const uint32_t kcol = (uint32_t)((lane >> 3) & 1) * 16;
    const uint32_t vrow = (uint32_t)((lane & 7) + ((lane >> 3) & 1) * 8);
    const uint32_t vcol = (uint32_t)(lane >> 4) * 16;
    const float SCL = 0.125f * 1.44269504f;   // 1/sqrt(64) * log2(e)

    for (int kb = 0; kb <= qb; kb++) {
        if (kb < qb) {
            const uint32_t nst = kv0 + (uint32_t)((kb + 1) & 1) * (4 * ATILE);
            const size_t   gof = hb + (size_t)(kb + 1) * 64 * DK;
            aload(nst + 0 * ATILE, g_kh + gof, tid);
            aload(nst + 1 * ATILE, g_kl + gof, tid);
            aload(nst + 2 * ATILE, g_vh + gof, tid);
            aload(nst + 3 * ATILE, g_vl + gof, tid);
            asm volatile("cp.async.commit_group;" ::: "memory");
            asm volatile("cp.async.wait_group 1;" ::: "memory");
        } else {
            asm volatile("cp.async.wait_group 0;" ::: "memory");
        }
        __syncthreads();

        const uint32_t st   = kv0 + (uint32_t)(kb & 1) * (4 * ATILE);
        const uint32_t kh_s = st, kl_s = st + ATILE;
        const uint32_t vh_s = st + 2 * ATILE, vl_s = st + 3 * ATILE;

        // ---- S = Q K^T (bf16x3) ----
        float sc[8][4];
        #pragma unroll
        for (int j = 0; j < 8; j++)
            #pragma unroll
            for (int c = 0; c < 4; c++) sc[j][c] = 0.0f;

        #pragma unroll
        for (int ks = 0; ks < 4; ks++) {
            uint32_t aqh[4], aql[4];
            ldsm4(aqh, qh_s + qoff + ks * 32);
            ldsm4(aql, ql_s + qoff + ks * 32);
            #pragma unroll
            for (int nb = 0; nb < 4; nb++) {
                uint32_t ra = (uint32_t)(nb * 16 + krow) * (ASTR * 2) + kcol + ks * 32;
                uint32_t bkh[4], bkl[4];
                ldsm4(bkh, kh_s + ra);
                ldsm4(bkl, kl_s + ra);
                mma16816(sc[2 * nb],     aqh, &bkh[0]);
                mma16816(sc[2 * nb],     aqh, &bkl[0]);
                mma16816(sc[2 * nb],     aql, &bkh[0]);
                mma16816(sc[2 * nb + 1], aqh, &bkh[2]);
                mma16816(sc[2 * nb + 1], aqh, &bkl[2]);
                mma16816(sc[2 * nb + 1], aql, &bkh[2]);
            }
        }

        // ---- scale (pre-multiplied by log2 e) + causal mask ----
        #pragma unroll
        for (int j = 0; j < 8; j++)
            #pragma unroll
            for (int c = 0; c < 4; c++) sc[j][c] *= SCL;
        if (kb == qb) {
            const int r0 = q0 + warp * 16 + (lane >> 2);
            #pragma unroll
            for (int j = 0; j < 8; j++)
                #pragma unroll
                for (int c = 0; c < 4; c++) {
                    const int col = kb * 64 + j * 8 + (lane & 3) * 2 + (c & 1);
                    const int row = r0 + (c >> 1) * 8;
                    if (col > row) sc[j][c] = -1e30f;
                }
        }

        // ---- online softmax (base-2, deferred sum) ----
        float mx0 = -1e30f, mx1 = -1e30f;
        #pragma unroll
        for (int j = 0; j < 8; j++) {
            mx0 = fmaxf(mx0, fmaxf(sc[j][0], sc[j][1]));
            mx1 = fmaxf(mx1, fmaxf(sc[j][2], sc[j][3]));
        }
        mx0 = fmaxf(mx0, __shfl_xor_sync(0xffffffffu, mx0, 1));
        mx0 = fmaxf(mx0, __shfl_xor_sync(0xffffffffu, mx0, 2));
        mx1 = fmaxf(mx1, __shfl_xor_sync(0xffffffffu, mx1, 1));
        mx1 = fmaxf(mx1, __shfl_xor_sync(0xffffffffu, mx1, 2));
        const float mn0 = fmaxf(m0, mx0), mn1 = fmaxf(m1, mx1);
        const float a0  = exp2f(m0 - mn0);
        const float a1  = exp2f(m1 - mn1);
        m0 = mn0; m1 = mn1;

        float s0 = 0.0f, s1 = 0.0f;
        #pragma unroll
        for (int j = 0; j < 8; j++) {
            sc[j][0] = exp2f(sc[j][0] - mn0);
            sc[j][1] = exp2f(sc[j][1] - mn0);
            sc[j][2] = exp2f(sc[j][2] - mn1);
            sc[j][3] = exp2f(sc[j][3] - mn1);
            s0 += sc[j][0] + sc[j][1];
            s1 += sc[j][2] + sc[j][3];
        }
        // per-thread partial update only — no shuffles here
        lp0 = lp0 * a0 + s0;
        lp1 = lp1 * a1 + s1;
        #pragma unroll
        for (int j = 0; j < 8; j++) {
            o[j][0] *= a0; o[j][1] *= a0;
            o[j][2] *= a1; o[j][3] *= a1;
        }

        // ---- O += P V (bf16x3, P repacked C->A in registers) ----
        #pragma unroll
        for (int j = 0; j < 4; j++) {
            const int t0 = 2 * j, t1 = 2 * j + 1;
            uint32_t ph[4], pl[4];
            ph[0] = packbf2(sc[t0][0], sc[t0][1]);
            ph[1] = packbf2(sc[t0][2], sc[t0][3]);
            ph[2] = packbf2(sc[t1][0], sc[t1][1]);
            ph[3] = packbf2(sc[t1][2], sc[t1][3]);
            {
                __nv_bfloat162 b0 = *(__nv_bfloat162*)&ph[0];
                __nv_bfloat162 b1 = *(__nv_bfloat162*)&ph[1];
                __nv_bfloat162 b2 = *(__nv_bfloat162*)&ph[2];
                __nv_bfloat162 b3 = *(__nv_bfloat162*)&ph[3];
                pl[0] = packbf2(sc[t0][0] - __low2float(b0), sc[t0][1] - __high2float(b0));
                pl[1] = packbf2(sc[t0][2] - __low2float(b1), sc[t0][3] - __high2float(b1));
                pl[2] = packbf2(sc[t1][0] - __low2float(b2), sc[t1][1] - __high2float(b2));
                pl[3] = packbf2(sc[t1][2] - __low2float(b3), sc[t1][3] - __high2float(b3));
            }
            #pragma unroll
            for (int nb = 0; nb < 4; nb++) {
                uint32_t ra = (uint32_t)(j * 16 + vrow) * (ASTR * 2) + vcol + nb * 32;
                uint32_t bvh[4], bvl[4];
                ldsm4t(bvh, vh_s + ra);
                ldsm4t(bvl, vl_s + ra);
                mma16816(o[2 * nb],     ph, &bvh[0]);
                mma16816(o[2 * nb],     ph, &bvl[0]);
                mma16816(o[2 * nb],     pl, &bvh[0]);
                mma16816(o[2 * nb + 1], ph, &bvh[2]);
                mma16816(o[2 * nb + 1], ph, &bvl[2]);
                mma16816(o[2 * nb + 1], pl, &bvh[2]);
            }
        }
        __syncthreads();
    }

    // ---- final l reduction (once), normalize + write bf16 hi/lo ----
    lp0 += __shfl_xor_sync(0xffffffffu, lp0, 1);
    lp0 += __shfl_xor_sync(0xffffffffu, lp0, 2);
    lp1 += __shfl_xor_sync(0xffffffffu, lp1, 1);
    lp1 += __shfl_xor_sync(0xffffffffu, lp1, 2);
    const float inv0 = 1.0f / lp0, inv1 = 1.0f / lp1;
    const int r  = q0 + warp * 16 + (lane >> 2);
    const int cb = h * 64 + (lane & 3) * 2;
    #pragma unroll
    for (int j = 0; j < 8; j++) {
        const int col = cb + j * 8;
        float f0 = o[j][0] * inv0, f1 = o[j][1] * inv0;
        float f2 = o[j][2] * inv1, f3 = o[j][3] * inv1;
        __nv_bfloat162 h0 = __float22bfloat162_rn(make_float2(f0, f1));
        __nv_bfloat162 h1 = __float22bfloat162_rn(make_float2(f2, f3));
        __nv_bfloat162 l0v = __float22bfloat162_rn(make_float2(
            f0 - __low2float(h0), f1 - __high2float(h0)));
        __nv_bfloat162 l1v = __float22bfloat162_rn(make_float2(
            f2 - __low2float(h1), f3 - __high2float(h1)));
        *(__nv_bfloat162*)&g_ah[(size_t)r * DM + col]       = h0;
        *(__nv_bfloat162*)&g_al[(size_t)r * DM + col]       = l0v;
        *(__nv_bfloat162*)&g_ah[(size_t)(r + 8) * DM + col] = h1;
        *(__nv_bfloat162*)&g_al[(size_t)(r + 8) * DM + col] = l1v;
    }
}

// ============================================================
// launch
// ============================================================
extern "C" void kernel_launch(void* const* d_in, const int* in_sizes, int n_in,
                              void* d_out, int out_size) {
    const float* x  = (const float*)d_in[0];
    const float* wq = (const float*)d_in[1];
    const float* wk = (const float*)d_in[2];
    const float* wv = (const float*)d_in[3];
    const float* wo = (const float*)d_in[4];
    float* out = (float*)d_out;

    __nv_bfloat16 *xh, *xl, *ah, *al;
    __nv_bfloat16 *wqh, *wql, *wkh, *wkl, *wvh, *wvl, *woh, *wol;
    __nv_bfloat16 *qh, *ql, *kh, *kl, *vh, *vl;
    cudaGetSymbolAddress((void**)&xh,  g_xh);
    cudaGetSymbolAddress((void**)&xl,  g_xl);
    cudaGetSymbolAddress((void**)&ah,  g_ah);
    cudaGetSymbolAddress((void**)&al,  g_al);
    cudaGetSymbolAddress((void**)&wqh, g_wqh);
    cudaGetSymbolAddress((void**)&wql, g_wql);
    cudaGetSymbolAddress((void**)&wkh, g_wkh);
    cudaGetSymbolAddress((void**)&wkl, g_wkl);
    cudaGetSymbolAddress((void**)&wvh, g_wvh);
    cudaGetSymbolAddress((void**)&wvl, g_wvl);
    cudaGetSymbolAddress((void**)&woh, g_woh);
    cudaGetSymbolAddress((void**)&wol, g_wol);
    cudaGetSymbolAddress((void**)&qh,  g_qh);
    cudaGetSymbolAddress((void**)&ql,  g_ql);
    cudaGetSymbolAddress((void**)&kh,  g_kh);
    cudaGetSymbolAddress((void**)&kl,  g_kl);
    cudaGetSymbolAddress((void**)&vh,  g_vh);
    cudaGetSymbolAddress((void**)&vl,  g_vl);

    cudaFuncSetAttribute(gemm_tc,
                         cudaFuncAttributeMaxDynamicSharedMemorySize, GEMM_SMEM);
    cudaFuncSetAttribute(attn_tc,
                         cudaFuncAttributeMaxDynamicSharedMemorySize, ATT_SMEM);

    const int nx4 = SEQ * DM / 4;
    const int nw4 = DM * DM / 4;

    rope_table_kernel<<<(SEQ * 32) / 256, 256>>>();
    conv_split<<<(nx4 + 255) / 256, 256>>>((const float4*)x,
                                           (__nv_bfloat162*)xh, (__nv_bfloat162*)xl, nx4);
    conv_split3<<<dim3((nw4 + 255) / 256, 3), 256>>>(
        (const float4*)wq, (const float4*)wk, (const float4*)wv,
        (__nv_bfloat162*)wqh, (__nv_bfloat162*)wql,
        (__nv_bfloat162*)wkh, (__nv_bfloat162*)wkl,
        (__nv_bfloat162*)wvh, (__nv_bfloat162*)wvl, nw4);
    conv_split<<<(nw4 + 255) / 256, 256>>>((const float4*)wo,
                                           (__nv_bfloat162*)woh, (__nv_bfloat162*)wol, nw4);

    // QKV: 24 N-tiles -> bf16 hi/lo head-major with fused RoPE
    gemm_tc<<<dim3(24, 32), 256, GEMM_SMEM>>>(xh, xl,
                                              wqh, wql, wkh, wkl, wvh, wvl,
                                              nullptr,
                                              qh, ql, kh, kl, vh, vl, 1);

    attn_tc<<<dim3(SEQ / 64, NH), 128, ATT_SMEM>>>();

    // Wo: fp32 out
    gemm_tc<<<dim3(8, 32), 256, GEMM_SMEM>>>(ah, al,
                                             woh, wol, woh, wol, woh, wol,
                                             out,
                                             nullptr, nullptr, nullptr,
                                             nullptr, nullptr, nullptr, 0);
}

// round 13
// speedup vs baseline: 1.1275x; 1.0747x over previous
#include <cuda_runtime.h>
#include <cuda_bf16.h>
#include <cuda_fp16.h>
#include <math.h>
#include <cstdint>

#define SEQ   4096
#define DM    1024
#define NH    16
#define DK    64

// ---- bf16 hi/lo buffers (GEMM operands) ----
__device__ __nv_bfloat16 g_xh[SEQ * DM], g_xl[SEQ * DM];
__device__ __nv_bfloat16 g_ah[SEQ * DM], g_al[SEQ * DM];   // attention output
__device__ __nv_bfloat16 g_wqh[DM * DM], g_wql[DM * DM];
__device__ __nv_bfloat16 g_wkh[DM * DM], g_wkl[DM * DM];
__device__ __nv_bfloat16 g_wvh[DM * DM], g_wvl[DM * DM];
__device__ __nv_bfloat16 g_woh[DM * DM], g_wol[DM * DM];
// head-major [NH][SEQ][DK] Q/K/V hi/lo in FP16 (22-bit combined precision)
__device__ __half g_qh[NH * SEQ * DK], g_ql[NH * SEQ * DK];
__device__ __half g_kh[NH * SEQ * DK], g_kl[NH * SEQ * DK];
__device__ __half g_vh[NH * SEQ * DK], g_vl[NH * SEQ * DK];

__device__ float g_rope_cos[SEQ * 32];
__device__ float g_rope_sin[SEQ * 32];

// ============================================================
// RoPE table (double trig, fp32 phase rounding like the reference)
// ============================================================
__global__ void rope_table_kernel() {
    int t = blockIdx.x * blockDim.x + threadIdx.x;
    int jj  = t & 31;
    int pos = t >> 5;
    if (pos >= SEQ) return;
    float invf = (float)pow(10000.0, -(double)jj / 32.0);
    float freq = (float)pos * invf;
    g_rope_cos[pos * 32 + jj] = (float)cos((double)freq);
    g_rope_sin[pos * 32 + jj] = (float)sin((double)freq);
}

// ============================================================
// fp32 -> (hi, lo) bf16 split
// ============================================================
__device__ __forceinline__ void split4(const float4 v,
                                       __nv_bfloat162* hi,
                                       __nv_bfloat162* lo, int i) {
    __nv_bfloat16 h0 = __float2bfloat16(v.x);
    __nv_bfloat16 h1 = __float2bfloat16(v.y);
    __nv_bfloat16 h2 = __float2bfloat16(v.z);
    __nv_bfloat16 h3 = __float2bfloat16(v.w);
    __nv_bfloat162 a, b, c, d;
    a.x = h0; a.y = h1;
    b.x = h2; b.y = h3;
    c.x = __float2bfloat16(v.x - __bfloat162float(h0));
    c.y = __float2bfloat16(v.y - __bfloat162float(h1));
    d.x = __float2bfloat16(v.z - __bfloat162float(h2));
    d.y = __float2bfloat16(v.w - __bfloat162float(h3));
    hi[2 * i + 0] = a;
    hi[2 * i + 1] = b;
    lo[2 * i + 0] = c;
    lo[2 * i + 1] = d;
}

__global__ void conv_split(const float4* __restrict__ src,
                           __nv_bfloat162* __restrict__ hi,
                           __nv_bfloat162* __restrict__ lo, int n4) {
    int i = blockIdx.x * blockDim.x + threadIdx.x;
    if (i >= n4) return;
    split4(src[i], hi, lo, i);
}

// batched: blockIdx.y selects (src, hi, lo) triple — wq/wk/wv in one launch
__global__ void conv_split3(const float4* __restrict__ s0,
                            const float4* __restrict__ s1,
                            const float4* __restrict__ s2,
                            __nv_bfloat162* __restrict__ h0, __nv_bfloat162* __restrict__ l0,
                            __nv_bfloat162* __restrict__ h1, __nv_bfloat162* __restrict__ l1,
                            __nv_bfloat162* __restrict__ h2, __nv_bfloat162* __restrict__ l2,
                            int n4) {
    int i = blockIdx.x * blockDim.x + threadIdx.x;
    if (i >= n4) return;
    const float4* src  = (blockIdx.y == 0) ? s0 : (blockIdx.y == 1) ? s1 : s2;
    __nv_bfloat162* hi = (blockIdx.y == 0) ? h0 : (blockIdx.y == 1) ? h1 : h2;
    __nv_bfloat162* lo = (blockIdx.y == 0) ? l0 : (blockIdx.y == 1) ? l1 : l2;
    split4(src[i], hi, lo, i);
}

// ============================================================
// warp-mma helpers
// ============================================================
__device__ __forceinline__ uint32_t s2u(const void* p) {
    uint32_t a;
    asm("{ .reg .u64 t; cvta.to.shared.u64 t, %1; cvt.u32.u64 %0, t; }"
        : "=r"(a) : "l"(p));
    return a;
}

// bf16 mma (GEMM path)
__device__ __forceinline__ void mma16816(float* d, const uint32_t* a,
                                         const uint32_t* b) {
    asm volatile(
        "mma.sync.aligned.m16n8k16.row.col.f32.bf16.bf16.f32 "
        "{%0,%1,%2,%3}, {%4,%5,%6,%7}, {%8,%9}, {%0,%1,%2,%3};"
        : "+f"(d[0]), "+f"(d[1]), "+f"(d[2]), "+f"(d[3])
        : "r"(a[0]), "r"(a[1]), "r"(a[2]), "r"(a[3]), "r"(b[0]), "r"(b[1]));
}

// fp16 mma (attention path)
__device__ __forceinline__ void mma16816h(float* d, const uint32_t* a,
                                          const uint32_t* b) {
    asm volatile(
        "mma.sync.aligned.m16n8k16.row.col.f32.f16.f16.f32 "
        "{%0,%1,%2,%3}, {%4,%5,%6,%7}, {%8,%9}, {%0,%1,%2,%3};"
        : "+f"(d[0]), "+f"(d[1]), "+f"(d[2]), "+f"(d[3])
        : "r"(a[0]), "r"(a[1]), "r"(a[2]), "r"(a[3]), "r"(b[0]), "r"(b[1]));
}

__device__ __forceinline__ void ldsm4(uint32_t* r, uint32_t addr) {
    asm volatile("ldmatrix.sync.aligned.m8n8.x4.shared.b16 {%0,%1,%2,%3}, [%4];"
                 : "=r"(r[0]), "=r"(r[1]), "=r"(r[2]), "=r"(r[3]) : "r"(addr));
}

__device__ __forceinline__ void ldsm4t(uint32_t* r, uint32_t addr) {
    asm volatile("ldmatrix.sync.aligned.m8n8.x4.trans.shared.b16 {%0,%1,%2,%3}, [%4];"
                 : "=r"(r[0]), "=r"(r[1]), "=r"(r[2]), "=r"(r[3]) : "r"(addr));
}

__device__ __forceinline__ void ldsm2(uint32_t* r, uint32_t addr) {
    asm volatile("ldmatrix.sync.aligned.m8n8.x2.shared.b16 {%0,%1}, [%2];"
                 : "=r"(r[0]), "=r"(r[1]) : "r"(addr));
}

__device__ __forceinline__ uint32_t packh2(float lo, float hi) {
    __half2 h = __float22half2_rn(make_float2(lo, hi));
    return *(uint32_t*)&h;
}

// ============================================================
// bf16x3 GEMM via mma.sync:  D[m,n] = sum_k A[m,k] * B[n,k]
// CTA 128x128, BK=32, 256 thr (8 warps, 64x32 warp tiles).
// mode 0: fp32 output. mode 1: QKV epilogue (RoPE + FP16 hi/lo head-major).
// ============================================================
#define KPAD      40
#define TILE_B    (128 * KPAD * 2)
#define STAGE_B   (4 * TILE_B)
#define GEMM_SMEM (2 * STAGE_B)

__device__ __forceinline__ void load_tile4(uint32_t st,
                                           const __nv_bfloat16* ah,
                                           const __nv_bfloat16* al,
                                           const __nv_bfloat16* bh,
                                           const __nv_bfloat16* bl, int tid) {
    #pragma unroll
    for (int i = 0; i < 2; i++) {
        int c   = tid + 256 * i;
        int row = c >> 2;
        int sg  = (c & 3) << 4;
        uint32_t soff = (uint32_t)row * (KPAD * 2) + (uint32_t)sg;
        size_t   goff = (size_t)row * (DM * 2) + sg;
        asm volatile("cp.async.cg.shared.global [%0], [%1], 16;"
                     :: "r"(st + 0 * TILE_B + soff), "l"((const char*)ah + goff) : "memory");
        asm volatile("cp.async.cg.shared.global [%0], [%1], 16;"
                     :: "r"(st + 1 * TILE_B + soff), "l"((const char*)al + goff) : "memory");
        asm volatile("cp.async.cg.shared.global [%0], [%1], 16;"
                     :: "r"(st + 2 * TILE_B + soff), "l"((const char*)bh + goff) : "memory");
        asm volatile("cp.async.cg.shared.global [%0], [%1], 16;"
                     :: "r"(st + 3 * TILE_B + soff), "l"((const char*)bl + goff) : "memory");
    }
}

__global__ void __launch_bounds__(256)
gemm_tc(const __nv_bfloat16* __restrict__ Ah, const __nv_bfloat16* __restrict__ Al,
        const __nv_bfloat16* __restrict__ B0h, const __nv_bfloat16* __restrict__ B0l,
        const __nv_bfloat16* __restrict__ B1h, const __nv_bfloat16* __restrict__ B1l,
        const __nv_bfloat16* __restrict__ B2h, const __nv_bfloat16* __restrict__ B2l,
        float* __restrict__ Dout,
        __half* __restrict__ Oqh, __half* __restrict__ Oql,
        __half* __restrict__ Okh, __half* __restrict__ Okl,
        __half* __restrict__ Ovh, __half* __restrict__ Ovl,
        int mode) {
    extern __shared__ char smraw[];
    const uint32_t sb = s2u(smraw);

    const int tid  = threadIdx.x;
    const int lane = tid & 31;
    const int wid  = tid >> 5;
    const int warp_m = (wid & 1) * 64;
    const int warp_n = (wid >> 1) * 32;

    const int ntile = blockIdx.x;
    const int which = ntile >> 3;
    const int nloc  = (ntile & 7) * 128;
    const int m0    = blockIdx.y * 128;

    const __nv_bfloat16* Bh = (which == 0) ? B0h : (which == 1) ? B1h : B2h;
    const __nv_bfloat16* Bl = (which == 0) ? B0l : (which == 1) ? B1l : B2l;

    const __nv_bfloat16* Abh = Ah + (size_t)m0 * DM;
    const __nv_bfloat16* Abl = Al + (size_t)m0 * DM;
    const __nv_bfloat16* Bbh = Bh + (size_t)nloc * DM;
    const __nv_bfloat16* Bbl = Bl + (size_t)nloc * DM;

    float acc[4][4][4];
    #pragma unroll
    for (int i = 0; i < 4; i++)
        #pragma unroll
        for (int j = 0; j < 4; j++)
            #pragma unroll
            for (int r = 0; r < 4; r++) acc[i][j][r] = 0.0f;

    const uint32_t a_off = (uint32_t)(lane & 15) * (KPAD * 2) + (uint32_t)(lane >> 4) * 16;
    const int bl16 = lane & 15;
    const uint32_t b_off = (uint32_t)(bl16 & 7) * (KPAD * 2) + (uint32_t)(bl16 >> 3) * 16;

    load_tile4(sb, Abh, Abl, Bbh, Bbl, tid);
    asm volatile("cp.async.commit_group;" ::: "memory");

    for (int kb = 0; kb < 32; kb++) {
        const uint32_t st = sb + (uint32_t)(kb & 1) * STAGE_B;
        if (kb + 1 < 32) {
            const int ko = (kb + 1) * 32;
            load_tile4(sb + (uint32_t)((kb + 1) & 1) * STAGE_B,
                       Abh + ko, Abl + ko, Bbh + ko, Bbl + ko, tid);
            asm volatile("cp.async.commit_group;" ::: "memory");
            asm volatile("cp.async.wait_group 1;" ::: "memory");
        } else {
            asm volatile("cp.async.wait_group 0;" ::: "memory");
        }
        __syncthreads();

        #pragma unroll
        for (int ks = 0; ks < 2; ks++) {
            const uint32_t k0b = (uint32_t)ks * 32;
            uint32_t ahf[4][4], alf[4][4], bhf[4][2], blf[4][2];
            #pragma unroll
            for (int mi = 0; mi < 4; mi++) {
                uint32_t ra = (uint32_t)(warp_m + mi * 16) * (KPAD * 2) + k0b + a_off;
                ldsm4(ahf[mi], st + 0 * TILE_B + ra);
                ldsm4(alf[mi], st + 1 * TILE_B + ra);
            }
            #pragma unroll
            for (int ni = 0; ni < 4; ni++) {
                uint32_t rb = (uint32_t)(warp_n + ni * 8) * (KPAD * 2) + k0b + b_off;
                ldsm2(bhf[ni], st + 2 * TILE_B + rb);
                ldsm2(blf[ni], st + 3 * TILE_B + rb);
            }
            #pragma unroll
            for (int mi = 0; mi < 4; mi++)
                #pragma unroll
                for (int ni = 0; ni < 4; ni++) {
                    mma16816(acc[mi][ni], ahf[mi], bhf[ni]);
                    mma16816(acc[mi][ni], ahf[mi], blf[ni]);
                    mma16816(acc[mi][ni], alf[mi], bhf[ni]);
                }
        }
        __syncthreads();
    }

    const int rope = (mode == 1) && (which < 2);
    __half* Wh = (which == 0) ? Oqh : (which == 1) ? Okh : Ovh;
    __half* Wl = (which == 0) ? Oql : (which == 1) ? Okl : Ovl;

    #pragma unroll
    for (int mi = 0; mi < 4; mi++) {
        #pragma unroll
        for (int ni = 0; ni < 4; ni++) {
            const int r0  = m0 + warp_m + mi * 16 + (lane >> 2);
            const int col = nloc + warp_n + ni * 8 + (lane & 3) * 2;
            float c0 = acc[mi][ni][0], c1 = acc[mi][ni][1];
            float c2 = acc[mi][ni][2], c3 = acc[mi][ni][3];
            if (rope) {
                const int jj = (col & (DK - 1)) >> 1;
                float cs = g_rope_cos[r0 * 32 + jj];
                float sn = g_rope_sin[r0 * 32 + jj];
                float e = c0, o = c1;
                c0 = cs * e - sn * o;
                c1 = sn * e + cs * o;
                cs = g_rope_cos[(r0 + 8) * 32 + jj];
                sn = g_rope_sin[(r0 + 8) * 32 + jj];
                e = c2; o = c3;
                c2 = cs * e - sn * o;
                c3 = sn * e + cs * o;
            }
            if (mode == 0) {
                *(float2*)&Dout[(size_t)r0 * DM + col]       = make_float2(c0, c1);
                *(float2*)&Dout[(size_t)(r0 + 8) * DM + col] = make_float2(c2, c3);
            } else {
                const int head = col >> 6;
                const int d    = col & 63;
                const size_t p0 = ((size_t)head * SEQ + r0) * DK + d;
                const size_t p1 = ((size_t)head * SEQ + r0 + 8) * DK + d;
                __half2 h0 = __float22half2_rn(make_float2(c0, c1));
                __half2 h1 = __float22half2_rn(make_float2(c2, c3));
                __half2 l0 = __float22half2_rn(make_float2(
                    c0 - __half2float(h0.x), c1 - __half2float(h0.y)));
                __half2 l1 = __float22half2_rn(make_float2(
                    c2 - __half2float(h1.x), c3 - __half2float(h1.y)));
                *(__half2*)&Wh[p0] = h0;
                *(__half2*)&Wh[p1] = h1;
                *(__half2*)&Wl[p0] = l0;
                *(__half2*)&Wl[p1] = l1;
            }
        }
    }
}

// ============================================================
// Tensor-core causal flash attention (fp16 operands).
// CTA = (head, 64-query block). 128 thr, 4 warps x 16 rows.
// QK^T: 3-term fp16 split (~2^-22 accurate).
// PV:   2-term (Ph*Vh + Ph*Vl); dropped Pl*Vh term ~2^-12 relative.
// Deferred row-sum reduction (once at end).
// ============================================================
#define ASTR  72                       // halves per smem row
#define ATILE (64 * ASTR * 2)          // 9216 B per 64x64 tile
#define ATT_SMEM (10 * ATILE)          // Qh,Ql + 2 stages x (Kh,Kl,Vh,Vl)

__device__ __forceinline__ void aload(uint32_t dst, const __half* src, int tid) {
    const char* s = (const char*)src;
    #pragma unroll
    for (int i = 0; i < 4; i++) {
        int c   = tid + 128 * i;
        int row = c >> 3;
        int seg = (c & 7) << 4;
        asm volatile("cp.async.cg.shared.global [%0], [%1], 16;"
                     :: "r"(dst + (uint32_t)row * (ASTR * 2) + (uint32_t)seg),
                        "l"(s + (size_t)row * 128 + seg) : "memory");
    }
}

__global__ void __launch_bounds__(128) attn_tc() {
    extern __shared__ char smraw[];
    const uint32_t sb   = s2u(smraw);
    const uint32_t qh_s = sb;
    const uint32_t ql_s = sb + ATILE;
    const uint32_t kv0  = sb + 2 * ATILE;   // + stage*4*ATILE: Kh,Kl,Vh,Vl

    const int tid  = threadIdx.x;
    const int lane = tid & 31;
    const int warp = tid >> 5;
    const int h    = blockIdx.y;
    const int qb   = gridDim.x - 1 - blockIdx.x;   // heavy-first
    const int q0   = qb * 64;

    const size_t hb = (size_t)h * SEQ * DK;

    // Q tile + KV block 0
    aload(qh_s, g_qh + hb + (size_t)q0 * DK, tid);
    aload(ql_s, g_ql + hb + (size_t)q0 * DK, tid);
    aload(kv0 + 0 * ATILE, g_kh + hb, tid);
    aload(kv0 + 1 * ATILE, g_kl + hb, tid);
    aload(kv0 + 2 * ATILE, g_vh + hb, tid);
    aload(kv0 + 3 * ATILE, g_vl + hb, tid);
    asm volatile("cp.async.commit_group;" ::: "memory");

    float o[8][4];
    #pragma unroll
    for (int j = 0; j < 8; j++)
        #pragma unroll
        for (int c = 0; c < 4; c++) o[j][c] = 0.0f;
    float m0 = -1e30f, m1 = -1e30f;
    float lp0 = 0.0f, lp1 = 0.0f;      // per-thread partial row sums

    const uint32_t qoff = (uint32_t)(warp * 16 + (lane & 15)) * (ASTR * 2)
                        + (uint32_t)(lane >> 4) * 16;
    const uint32_t krow = (uint32_t)((lane & 7) + ((lane >> 4) & 1) * 8);
    const uint32_t kcol = (uint32_t)((lane >> 3) & 1) * 16;
    const uint32_t vrow = (uint32_t)((lane & 7) + ((lane >> 3) & 1) * 8);
    const uint32_t vcol = (uint32_t)(lane >> 4) * 16;
    const float SCL = 0.125f * 1.44269504f;   // 1/sqrt(64) * log2(e)

    for (int kb = 0; kb <= qb; kb++) {
        if (kb < qb) {
            const uint32_t nst = kv0 + (uint32_t)((kb + 1) & 1) * (4 * ATILE);
            const size_t   gof = hb + (size_t)(kb + 1) * 64 * DK;
            aload(nst + 0 * ATILE, g_kh + gof, tid);
            aload(nst + 1 * ATILE, g_kl + gof, tid);
            aload(nst + 2 * ATILE, g_vh + gof, tid);
            aload(nst + 3 * ATILE, g_vl + gof, tid);
            asm volatile("cp.async.commit_group;" ::: "memory");
            asm volatile("cp.async.wait_group 1;" ::: "memory");
        } else {
            asm volatile("cp.async.wait_group 0;" ::: "memory");
        }
        __syncthreads();

        const uint32_t st   = kv0 + (uint32_t)(kb & 1) * (4 * ATILE);
        const uint32_t kh_s = st, kl_s = st + ATILE;
        const uint32_t vh_s = st + 2 * ATILE, vl_s = st + 3 * ATILE;

        // ---- S = Q K^T (fp16 x3: QhKh + QhKl + QlKh) ----
        float sc[8][4];
        #pragma unroll
        for (int j = 0; j < 8; j++)
            #pragma unroll
            for (int c = 0; c < 4; c++) sc[j][c] = 0.0f;

        #pragma unroll
        for (int ks = 0; ks < 4; ks++) {
            uint32_t aqh[4], aql[4];
            ldsm4(aqh, qh_s + qoff + ks * 32);
            ldsm4(aql, ql_s + qoff + ks * 32);
            #pragma unroll
            for (int nb = 0; nb < 4; nb++) {
                uint32_t ra = (uint32_t)(nb * 16 + krow) * (ASTR * 2) + kcol + ks * 32;
                uint32_t bkh[4], bkl[4];
                ldsm4(bkh, kh_s + ra);
                ldsm4(bkl, kl_s + ra);
                mma16816h(sc[2 * nb],     aqh, &bkh[0]);
                mma16816h(sc[2 * nb],     aqh, &bkl[0]);
                mma16816h(sc[2 * nb],     aql, &bkh[0]);
                mma16816h(sc[2 * nb + 1], aqh, &bkh[2]);
                mma16816h(sc[2 * nb + 1], aqh, &bkl[2]);
                mma16816h(sc[2 * nb + 1], aql, &bkh[2]);
            }
        }

        // ---- scale (pre-multiplied by log2 e) + causal mask ----
        #pragma unroll
        for (int j = 0; j < 8; j++)
            #pragma unroll
            for (int c = 0; c < 4; c++) sc[j][c] *= SCL;
        if (kb == qb) {
            const int r0 = q0 + warp * 16 + (lane >> 2);
            #pragma unroll
            for (int j = 0; j < 8; j++)
                #pragma unroll
                for (int c = 0; c < 4; c++) {
                    const int col = kb * 64 + j * 8 + (lane & 3) * 2 + (c & 1);
                    const int row = r0 + (c >> 1) * 8;
                    if (col > row) sc[j][c] = -1e30f;
                }
        }

        // ---- online softmax (base-2, deferred sum) ----
        float mx0 = -1e30f, mx1 = -1e30f;
        #pragma unroll
        for (int j = 0; j < 8; j++) {
            mx0 = fmaxf(mx0, fmaxf(sc[j][0], sc[j][1]));
            mx1 = fmaxf(mx1, fmaxf(sc[j][2], sc[j][3]));
        }
        mx0 = fmaxf(mx0, __shfl_xor_sync(0xffffffffu, mx0, 1));
        mx0 = fmaxf(mx0, __shfl_xor_sync(0xffffffffu, mx0, 2));
        mx1 = fmaxf(mx1, __shfl_xor_sync(0xffffffffu, mx1, 1));
        mx1 = fmaxf(mx1, __shfl_xor_sync(0xffffffffu, mx1, 2));
        const float mn0 = fmaxf(m0, mx0), mn1 = fmaxf(m1, mx1);
        const float a0  = exp2f(m0 - mn0);
        const float a1  = exp2f(m1 - mn1);
        m0 = mn0; m1 = mn1;

        float s0 = 0.0f, s1 = 0.0f;
        #pragma unroll
        for (int j = 0; j < 8; j++) {
            sc[j][0] = exp2f(sc[j][0] - mn0);
            sc[j][1] = exp2f(sc[j][1] - mn0);
            sc[j][2] = exp2f(sc[j][2] - mn1);
            sc[j][3] = exp2f(sc[j][3] - mn1);
            s0 += sc[j][0] + sc[j][1];
            s1 += sc[j][2] + sc[j][3];
        }
        lp0 = lp0 * a0 + s0;
        lp1 = lp1 * a1 + s1;
        #pragma unroll
        for (int j = 0; j < 8; j++) {
            o[j][0] *= a0; o[j][1] *= a0;
            o[j][2] *= a1; o[j][3] *= a1;
        }

        // ---- O += P V (fp16: Ph*Vh + Ph*Vl; Pl term dropped) ----
        #pragma unroll
        for (int j = 0; j < 4; j++) {
            const int t0 = 2 * j, t1 = 2 * j + 1;
            uint32_t ph[4];
            ph[0] = packh2(sc[t0][0], sc[t0][1]);
            ph[1] = packh2(sc[t0][2], sc[t0][3]);
            ph[2] = packh2(sc[t1][0], sc[t1][1]);
            ph[3] = packh2(sc[t1][2], sc[t1][3]);
            #pragma unroll
            for (int nb = 0; nb < 4; nb++) {
                uint32_t ra = (uint32_t)(j * 16 + vrow) * (ASTR * 2) + vcol + nb * 32;
                uint32_t bvh[4], bvl[4];
                ldsm4t(bvh, vh_s + ra);
                ldsm4t(bvl, vl_s + ra);
                mma16816h(o[2 * nb],     ph, &bvh[0]);
                mma16816h(o[2 * nb],     ph, &bvl[0]);
                mma16816h(o[2 * nb + 1], ph, &bvh[2]);
                mma16816h(o[2 * nb + 1], ph, &bvl[2]);
            }
        }
        __syncthreads();
    }

    // ---- final l reduction (once), normalize + write bf16 hi/lo ----
    lp0 += __shfl_xor_sync(0xffffffffu, lp0, 1);
    lp0 += __shfl_xor_sync(0xffffffffu, lp0, 2);
    lp1 += __shfl_xor_sync(0xffffffffu, lp1, 1);
    lp1 += __shfl_xor_sync(0xffffffffu, lp1, 2);
    const float inv0 = 1.0f / lp0, inv1 = 1.0f / lp1;
    const int r  = q0 + warp * 16 + (lane >> 2);
    const int cb = h * 64 + (lane & 3) * 2;
    #pragma unroll
    for (int j = 0; j < 8; j++) {
        const int col = cb + j * 8;
        float f0 = o[j][0] * inv0, f1 = o[j][1] * inv0;
        float f2 = o[j][2] * inv1, f3 = o[j][3] * inv1;
        __nv_bfloat162 h0 = __float22bfloat162_rn(make_float2(f0, f1));
        __nv_bfloat162 h1 = __float22bfloat162_rn(make_float2(f2, f3));
        __nv_bfloat162 l0v = __float22bfloat162_rn(make_float2(
            f0 - __low2float(h0), f1 - __high2float(h0)));
        __nv_bfloat162 l1v = __float22bfloat162_rn(make_float2(
            f2 - __low2float(h1), f3 - __high2float(h1)));
        *(__nv_bfloat162*)&g_ah[(size_t)r * DM + col]       = h0;
        *(__nv_bfloat162*)&g_al[(size_t)r * DM + col]       = l0v;
        *(__nv_bfloat162*)&g_ah[(size_t)(r + 8) * DM + col] = h1;
        *(__nv_bfloat162*)&g_al[(size_t)(r + 8) * DM + col] = l1v;
    }
}

// ============================================================
// launch
// ============================================================
extern "C" void kernel_launch(void* const* d_in, const int* in_sizes, int n_in,
                              void* d_out, int out_size) {
    const float* x  = (const float*)d_in[0];
    const float* wq = (const float*)d_in[1];
    const float* wk = (const float*)d_in[2];
    const float* wv = (const float*)d_in[3];
    const float* wo = (const float*)d_in[4];
    float* out = (float*)d_out;

    __nv_bfloat16 *xh, *xl, *ah, *al;
    __nv_bfloat16 *wqh, *wql, *wkh, *wkl, *wvh, *wvl, *woh, *wol;
    __half *qh, *ql, *kh, *kl, *vh, *vl;
    cudaGetSymbolAddress((void**)&xh,  g_xh);
    cudaGetSymbolAddress((void**)&xl,  g_xl);
    cudaGetSymbolAddress((void**)&ah,  g_ah);
    cudaGetSymbolAddress((void**)&al,  g_al);
    cudaGetSymbolAddress((void**)&wqh, g_wqh);
    cudaGetSymbolAddress((void**)&wql, g_wql);
    cudaGetSymbolAddress((void**)&wkh, g_wkh);
    cudaGetSymbolAddress((void**)&wkl, g_wkl);
    cudaGetSymbolAddress((void**)&wvh, g_wvh);
    cudaGetSymbolAddress((void**)&wvl, g_wvl);
    cudaGetSymbolAddress((void**)&woh, g_woh);
    cudaGetSymbolAddress((void**)&wol, g_wol);
    cudaGetSymbolAddress((void**)&qh,  g_qh);
    cudaGetSymbolAddress((void**)&ql,  g_ql);
    cudaGetSymbolAddress((void**)&kh,  g_kh);
    cudaGetSymbolAddress((void**)&kl,  g_kl);
    cudaGetSymbolAddress((void**)&vh,  g_vh);
    cudaGetSymbolAddress((void**)&vl,  g_vl);

    cudaFuncSetAttribute(gemm_tc,
                         cudaFuncAttributeMaxDynamicSharedMemorySize, GEMM_SMEM);
    cudaFuncSetAttribute(attn_tc,
                         cudaFuncAttributeMaxDynamicSharedMemorySize, ATT_SMEM);

    const int nx4 = SEQ * DM / 4;
    const int nw4 = DM * DM / 4;

    rope_table_kernel<<<(SEQ * 32) / 256, 256>>>();
    conv_split<<<(nx4 + 255) / 256, 256>>>((const float4*)x,
                                           (__nv_bfloat162*)xh, (__nv_bfloat162*)xl, nx4);
    conv_split3<<<dim3((nw4 + 255) / 256, 3), 256>>>(
        (const float4*)wq, (const float4*)wk, (const float4*)wv,
        (__nv_bfloat162*)wqh, (__nv_bfloat162*)wql,
        (__nv_bfloat162*)wkh, (__nv_bfloat162*)wkl,
        (__nv_bfloat162*)wvh, (__nv_bfloat162*)wvl, nw4);
    conv_split<<<(nw4 + 255) / 256, 256>>>((const float4*)wo,
                                           (__nv_bfloat162*)woh, (__nv_bfloat162*)wol, nw4);

    // QKV: 24 N-tiles -> FP16 hi/lo head-major with fused RoPE
    gemm_tc<<<dim3(24, 32), 256, GEMM_SMEM>>>(xh, xl,
                                              wqh, wql, wkh, wkl, wvh, wvl,
                                              nullptr,
                                              qh, ql, kh, kl, vh, vl, 1);

    attn_tc<<<dim3(SEQ / 64, NH), 128, ATT_SMEM>>>();

    // Wo: fp32 out
    gemm_tc<<<dim3(8, 32), 256, GEMM_SMEM>>>(ah, al,
                                             woh, wol, woh, wol, woh, wol,
                                             out,
                                             nullptr, nullptr, nullptr,
                                             nullptr, nullptr, nullptr, 0);
}

// round 14
// speedup vs baseline: 1.2384x; 1.0984x over previous
#include <cuda_runtime.h>
#include <cuda_bf16.h>
#include <cuda_fp16.h>
#include <math.h>
#include <cstdint>

#define SEQ   4096
#define DM    1024
#define NH    16
#define DK    64

// ---- fp16 hi/lo buffers (all tensor-core operands) ----
__device__ __half g_xh[SEQ * DM], g_xl[SEQ * DM];
__device__ __half g_ah[SEQ * DM], g_al[SEQ * DM];   // attention output
__device__ __half g_wqh[DM * DM], g_wql[DM * DM];
__device__ __half g_wkh[DM * DM], g_wkl[DM * DM];
__device__ __half g_wvh[DM * DM], g_wvl[DM * DM];
__device__ __half g_woh[DM * DM], g_wol[DM * DM];
// head-major [NH][SEQ][DK] Q/K/V hi/lo
__device__ __half g_qh[NH * SEQ * DK], g_ql[NH * SEQ * DK];
__device__ __half g_kh[NH * SEQ * DK], g_kl[NH * SEQ * DK];
__device__ __half g_vh[NH * SEQ * DK], g_vl[NH * SEQ * DK];

__device__ float g_rope_cos[SEQ * 32];
__device__ float g_rope_sin[SEQ * 32];

// ============================================================
// RoPE table (double trig, fp32 phase rounding like the reference)
// ============================================================
__global__ void rope_table_kernel() {
    int t = blockIdx.x * blockDim.x + threadIdx.x;
    int jj  = t & 31;
    int pos = t >> 5;
    if (pos >= SEQ) return;
    float invf = (float)pow(10000.0, -(double)jj / 32.0);
    float freq = (float)pos * invf;
    g_rope_cos[pos * 32 + jj] = (float)cos((double)freq);
    g_rope_sin[pos * 32 + jj] = (float)sin((double)freq);
}

// ============================================================
// fp32 -> (hi, lo) fp16 split (combined 22-bit mantissa)
// ============================================================
__device__ __forceinline__ void split4(const float4 v,
                                       __half2* hi, __half2* lo, int i) {
    __half2 a = __float22half2_rn(make_float2(v.x, v.y));
    __half2 b = __float22half2_rn(make_float2(v.z, v.w));
    __half2 c = __float22half2_rn(make_float2(v.x - __half2float(a.x),
                                              v.y - __half2float(a.y)));
    __half2 d = __float22half2_rn(make_float2(v.z - __half2float(b.x),
                                              v.w - __half2float(b.y)));
    hi[2 * i + 0] = a;
    hi[2 * i + 1] = b;
    lo[2 * i + 0] = c;
    lo[2 * i + 1] = d;
}

__global__ void conv_split(const float4* __restrict__ src,
                           __half2* __restrict__ hi,
                           __half2* __restrict__ lo, int n4) {
    int i = blockIdx.x * blockDim.x + threadIdx.x;
    if (i >= n4) return;
    split4(src[i], hi, lo, i);
}

__global__ void conv_split3(const float4* __restrict__ s0,
                            const float4* __restrict__ s1,
                            const float4* __restrict__ s2,
                            __half2* __restrict__ h0, __half2* __restrict__ l0,
                            __half2* __restrict__ h1, __half2* __restrict__ l1,
                            __half2* __restrict__ h2, __half2* __restrict__ l2,
                            int n4) {
    int i = blockIdx.x * blockDim.x + threadIdx.x;
    if (i >= n4) return;
    const float4* src = (blockIdx.y == 0) ? s0 : (blockIdx.y == 1) ? s1 : s2;
    __half2* hi       = (blockIdx.y == 0) ? h0 : (blockIdx.y == 1) ? h1 : h2;
    __half2* lo       = (blockIdx.y == 0) ? l0 : (blockIdx.y == 1) ? l1 : l2;
    split4(src[i], hi, lo, i);
}

// ============================================================
// warp-mma helpers (fp16 everywhere)
// ============================================================
__device__ __forceinline__ uint32_t s2u(const void* p) {
    uint32_t a;
    asm("{ .reg .u64 t; cvta.to.shared.u64 t, %1; cvt.u32.u64 %0, t; }"
        : "=r"(a) : "l"(p));
    return a;
}

__device__ __forceinline__ void mma16816h(float* d, const uint32_t* a,
                                          const uint32_t* b) {
    asm volatile(
        "mma.sync.aligned.m16n8k16.row.col.f32.f16.f16.f32 "
        "{%0,%1,%2,%3}, {%4,%5,%6,%7}, {%8,%9}, {%0,%1,%2,%3};"
        : "+f"(d[0]), "+f"(d[1]), "+f"(d[2]), "+f"(d[3])
        : "r"(a[0]), "r"(a[1]), "r"(a[2]), "r"(a[3]), "r"(b[0]), "r"(b[1]));
}

__device__ __forceinline__ void ldsm4(uint32_t* r, uint32_t addr) {
    asm volatile("ldmatrix.sync.aligned.m8n8.x4.shared.b16 {%0,%1,%2,%3}, [%4];"
                 : "=r"(r[0]), "=r"(r[1]), "=r"(r[2]), "=r"(r[3]) : "r"(addr));
}

__device__ __forceinline__ void ldsm4t(uint32_t* r, uint32_t addr) {
    asm volatile("ldmatrix.sync.aligned.m8n8.x4.trans.shared.b16 {%0,%1,%2,%3}, [%4];"
                 : "=r"(r[0]), "=r"(r[1]), "=r"(r[2]), "=r"(r[3]) : "r"(addr));
}

__device__ __forceinline__ void ldsm2(uint32_t* r, uint32_t addr) {
    asm volatile("ldmatrix.sync.aligned.m8n8.x2.shared.b16 {%0,%1}, [%2];"
                 : "=r"(r[0]), "=r"(r[1]) : "r"(addr));
}

__device__ __forceinline__ uint32_t packh2(float lo, float hi) {
    __half2 h = __float22half2_rn(make_float2(lo, hi));
    return *(uint32_t*)&h;
}

// ============================================================
// fp16 split GEMM via mma.sync:  D[m,n] = sum_k A[m,k] * B[n,k]
// 3 terms (AhBh+AhBl+AlBh, ~2^-22) for Q/K; 2 terms (AhBh+AhBl,
// ~2^-12 rel, linear error path) for V and Wo.
// CTA 128x128, BK=32, 256 thr (8 warps, 64x32 warp tiles).
// mode 0: fp32 out (Wo). mode 1: QKV epilogue (RoPE + fp16 hi/lo).
// ============================================================
#define KPAD      40
#define TILE_B    (128 * KPAD * 2)
#define STAGE_B   (4 * TILE_B)
#define GEMM_SMEM (2 * STAGE_B)

__device__ __forceinline__ void load_tile4(uint32_t st,
                                           const __half* ah, const __half* al,
                                           const __half* bh, const __half* bl,
                                           int tid, bool need_al) {
    #pragma unroll
    for (int i = 0; i < 2; i++) {
        int c   = tid + 256 * i;
        int row = c >> 2;
        int sg  = (c & 3) << 4;
        uint32_t soff = (uint32_t)row * (KPAD * 2) + (uint32_t)sg;
        size_t   goff = (size_t)row * (DM * 2) + sg;
        asm volatile("cp.async.cg.shared.global [%0], [%1], 16;"
                     :: "r"(st + 0 * TILE_B + soff), "l"((const char*)ah + goff) : "memory");
        if (need_al)
            asm volatile("cp.async.cg.shared.global [%0], [%1], 16;"
                         :: "r"(st + 1 * TILE_B + soff), "l"((const char*)al + goff) : "memory");
        asm volatile("cp.async.cg.shared.global [%0], [%1], 16;"
                     :: "r"(st + 2 * TILE_B + soff), "l"((const char*)bh + goff) : "memory");
        asm volatile("cp.async.cg.shared.global [%0], [%1], 16;"
                     :: "r"(st + 3 * TILE_B + soff), "l"((const char*)bl + goff) : "memory");
    }
}

__global__ void __launch_bounds__(256)
gemm_tc(const __half* __restrict__ Ah, const __half* __restrict__ Al,
        const __half* __restrict__ B0h, const __half* __restrict__ B0l,
        const __half* __restrict__ B1h, const __half* __restrict__ B1l,
        const __half* __restrict__ B2h, const __half* __restrict__ B2l,
        float* __restrict__ Dout,
        __half* __restrict__ Oqh, __half* __restrict__ Oql,
        __half* __restrict__ Okh, __half* __restrict__ Okl,
        __half* __restrict__ Ovh, __half* __restrict__ Ovl,
        int mode) {
    extern __shared__ char smraw[];
    const uint32_t sb = s2u(smraw);

    const int tid  = threadIdx.x;
    const int lane = tid & 31;
    const int wid  = tid >> 5;
    const int warp_m = (wid & 1) * 64;
    const int warp_n = (wid >> 1) * 32;

    const int ntile = blockIdx.x;
    const int which = ntile >> 3;
    const int nloc  = (ntile & 7) * 128;
    const int m0    = blockIdx.y * 128;

    const __half* Bh = (which == 0) ? B0h : (which == 1) ? B1h : B2h;
    const __half* Bl = (which == 0) ? B0l : (which == 1) ? B1l : B2l;

    // 3 terms only for Q/K projections (softmax-exponent-amplified path)
    const bool t3 = (mode == 1) && (which < 2);

    const __half* Abh = Ah + (size_t)m0 * DM;
    const __half* Abl = Al + (size_t)m0 * DM;
    const __half* Bbh = Bh + (size_t)nloc * DM;
    const __half* Bbl = Bl + (size_t)nloc * DM;

    float acc[4][4][4];
    #pragma unroll
    for (int i = 0; i < 4; i++)
        #pragma unroll
        for (int j = 0; j < 4; j++)
            #pragma unroll
            for (int r = 0; r < 4; r++) acc[i][j][r] = 0.0f;

    const uint32_t a_off = (uint32_t)(lane & 15) * (KPAD * 2) + (uint32_t)(lane >> 4) * 16;
    const int bl16 = lane & 15;
    const uint32_t b_off = (uint32_t)(bl16 & 7) * (KPAD * 2) + (uint32_t)(bl16 >> 3) * 16;

    load_tile4(sb, Abh, Abl, Bbh, Bbl, tid, t3);
    asm volatile("cp.async.commit_group;" ::: "memory");

    for (int kb = 0; kb < 32; kb++) {
        const uint32_t st = sb + (uint32_t)(kb & 1) * STAGE_B;
        if (kb + 1 < 32) {
            const int ko = (kb + 1) * 32;
            load_tile4(sb + (uint32_t)((kb + 1) & 1) * STAGE_B,
                       Abh + ko, Abl + ko, Bbh + ko, Bbl + ko, tid, t3);
            asm volatile("cp.async.commit_group;" ::: "memory");
            asm volatile("cp.async.wait_group 1;" ::: "memory");
        } else {
            asm volatile("cp.async.wait_group 0;" ::: "memory");
        }
        __syncthreads();

        #pragma unroll
        for (int ks = 0; ks < 2; ks++) {
            const uint32_t k0b = (uint32_t)ks * 32;
            uint32_t ahf[4][4], bhf[4][2], blf[4][2];
            #pragma unroll
            for (int mi = 0; mi < 4; mi++) {
                uint32_t ra = (uint32_t)(warp_m + mi * 16) * (KPAD * 2) + k0b + a_off;
                ldsm4(ahf[mi], st + 0 * TILE_B + ra);
            }
            #pragma unroll
            for (int ni = 0; ni < 4; ni++) {
                uint32_t rb = (uint32_t)(warp_n + ni * 8) * (KPAD * 2) + k0b + b_off;
                ldsm2(bhf[ni], st + 2 * TILE_B + rb);
                ldsm2(blf[ni], st + 3 * TILE_B + rb);
            }
            #pragma unroll
            for (int mi = 0; mi < 4; mi++)
                #pragma unroll
                for (int ni = 0; ni < 4; ni++) {
                    mma16816h(acc[mi][ni], ahf[mi], bhf[ni]);
                    mma16816h(acc[mi][ni], ahf[mi], blf[ni]);
                }
            if (t3) {   // uniform per-CTA branch, once per ks-step
                uint32_t alf[4][4];
                #pragma unroll
                for (int mi = 0; mi < 4; mi++) {
                    uint32_t ra = (uint32_t)(warp_m + mi * 16) * (KPAD * 2) + k0b + a_off;
                    ldsm4(alf[mi], st + 1 * TILE_B + ra);
                }
                #pragma unroll
                for (int mi = 0; mi < 4; mi++)
                    #pragma unroll
                    for (int ni = 0; ni < 4; ni++)
                        mma16816h(acc[mi][ni], alf[mi], bhf[ni]);
            }
        }
        __syncthreads();
    }

    const int rope = (mode == 1) && (which < 2);
    __half* Wh = (which == 0) ? Oqh : (which == 1) ? Okh : Ovh;
    __half* Wl = (which == 0) ? Oql : (which == 1) ? Okl : Ovl;

    #pragma unroll
    for (int mi = 0; mi < 4; mi++) {
        #pragma unroll
        for (int ni = 0; ni < 4; ni++) {
            const int r0  = m0 + warp_m + mi * 16 + (lane >> 2);
            const int col = nloc + warp_n + ni * 8 + (lane & 3) * 2;
            float c0 = acc[mi][ni][0], c1 = acc[mi][ni][1];
            float c2 = acc[mi][ni][2], c3 = acc[mi][ni][3];
            if (rope) {
                const int jj = (col & (DK - 1)) >> 1;
                float cs = g_rope_cos[r0 * 32 + jj];
                float sn = g_rope_sin[r0 * 32 + jj];
                float e = c0, o = c1;
                c0 = cs * e - sn * o;
                c1 = sn * e + cs * o;
                cs = g_rope_cos[(r0 + 8) * 32 + jj];
                sn = g_rope_sin[(r0 + 8) * 32 + jj];
                e = c2; o = c3;
                c2 = cs * e - sn * o;
                c3 = sn * e + cs * o;
            }
            if (mode == 0) {
                *(float2*)&Dout[(size_t)r0 * DM + col]       = make_float2(c0, c1);
                *(float2*)&Dout[(size_t)(r0 + 8) * DM + col] = make_float2(c2, c3);
            } else {
                const int head = col >> 6;
                const int d    = col & 63;
                const size_t p0 = ((size_t)head * SEQ + r0) * DK + d;
                const size_t p1 = ((size_t)head * SEQ + r0 + 8) * DK + d;
                __half2 h0 = __float22half2_rn(make_float2(c0, c1));
                __half2 h1 = __float22half2_rn(make_float2(c2, c3));
                __half2 l0 = __float22half2_rn(make_float2(
                    c0 - __half2float(h0.x), c1 - __half2float(h0.y)));
                __half2 l1 = __float22half2_rn(make_float2(
                    c2 - __half2float(h1.x), c3 - __half2float(h1.y)));
                *(__half2*)&Wh[p0] = h0;
                *(__half2*)&Wh[p1] = h1;
                *(__half2*)&Wl[p0] = l0;
                *(__half2*)&Wl[p1] = l1;
            }
        }
    }
}

// ============================================================
// Tensor-core causal flash attention (fp16, unchanged from r13).
// CTA = (head, 64-query block). 128 thr, 4 warps x 16 rows.
// QK^T: 3-term fp16 split. PV: 2-term. Deferred row-sum.
// ============================================================
#define ASTR  72
#define ATILE (64 * ASTR * 2)
#define ATT_SMEM (10 * ATILE)

__device__ __forceinline__ void aload(uint32_t dst, const __half* src, int tid) {
    const char* s = (const char*)src;
    #pragma unroll
    for (int i = 0; i < 4; i++) {
        int c   = tid + 128 * i;
        int row = c >> 3;
        int seg = (c & 7) << 4;
        asm volatile("cp.async.cg.shared.global [%0], [%1], 16;"
                     :: "r"(dst + (uint32_t)row * (ASTR * 2) + (uint32_t)seg),
                        "l"(s + (size_t)row * 128 + seg) : "memory");
    }
}

__global__ void __launch_bounds__(128) attn_tc() {
    extern __shared__ char smraw[];
    const uint32_t sb   = s2u(smraw);
    const uint32_t qh_s = sb;
    const uint32_t ql_s = sb + ATILE;
    const uint32_t kv0  = sb + 2 * ATILE;

    const int tid  = threadIdx.x;
    const int lane = tid & 31;
    const int warp = tid >> 5;
    const int h    = blockIdx.y;
    const int qb   = gridDim.x - 1 - blockIdx.x;
    const int q0   = qb * 64;

    const size_t hb = (size_t)h * SEQ * DK;

    aload(qh_s, g_qh + hb + (size_t)q0 * DK, tid);
    aload(ql_s, g_ql + hb + (size_t)q0 * DK, tid);
    aload(kv0 + 0 * ATILE, g_kh + hb, tid);
    aload(kv0 + 1 * ATILE, g_kl + hb, tid);
    aload(kv0 + 2 * ATILE, g_vh + hb, tid);
    aload(kv0 + 3 * ATILE, g_vl + hb, tid);
    asm volatile("cp.async.commit_group;" ::: "memory");

    float o[8][4];
    #pragma unroll
    for (int j = 0; j < 8; j++)
        #pragma unroll
        for (int c = 0; c < 4; c++) o[j][c] = 0.0f;
    float m0 = -1e30f, m1 = -1e30f;
    float lp0 = 0.0f, lp1 = 0.0f;

    const uint32_t qoff = (uint32_t)(warp * 16 + (lane & 15)) * (ASTR * 2)
                        + (uint32_t)(lane >> 4) * 16;
    const uint32_t krow = (uint32_t)((lane & 7) + ((lane >> 4) & 1) * 8);
    const uint32_t kcol = (uint32_t)((lane >> 3) & 1) * 16;
    const uint32_t vrow = (uint32_t)((lane & 7) + ((lane >> 3) & 1) * 8);
    const uint32_t vcol = (uint32_t)(lane >> 4) * 16;
    const float SCL = 0.125f * 1.44269504f;

    for (int kb = 0; kb <= qb; kb++) {
        if (kb < qb) {
            const uint32_t nst = kv0 + (uint32_t)((kb + 1) & 1) * (4 * ATILE);
            const size_t   gof = hb + (size_t)(kb + 1) * 64 * DK;
            aload(nst + 0 * ATILE, g_kh + gof, tid);
            aload(nst + 1 * ATILE, g_kl + gof, tid);
            aload(nst + 2 * ATILE, g_vh + gof, tid);
            aload(nst + 3 * ATILE, g_vl + gof, tid);
            asm volatile("cp.async.commit_group;" ::: "memory");
            asm volatile("cp.async.wait_group 1;" ::: "memory");
        } else {
            asm volatile("cp.async.wait_group 0;" ::: "memory");
        }
        __syncthreads();

        const uint32_t st   = kv0 + (uint32_t)(kb & 1) * (4 * ATILE);
        const uint32_t kh_s = st, kl_s = st + ATILE;
        const uint32_t vh_s = st + 2 * ATILE, vl_s = st + 3 * ATILE;

        float sc[8][4];
        #pragma unroll
        for (int j = 0; j < 8; j++)
            #pragma unroll
            for (int c = 0; c < 4; c++) sc[j][c] = 0.0f;

        #pragma unroll
        for (int ks = 0; ks < 4; ks++) {
            uint32_t aqh[4], aql[4];
            ldsm4(aqh, qh_s + qoff + ks * 32);
            ldsm4(aql, ql_s + qoff + ks * 32);
            #pragma unroll
            for (int nb = 0; nb < 4; nb++) {
                uint32_t ra = (uint32_t)(nb * 16 + krow) * (ASTR * 2) + kcol + ks * 32;
                uint32_t bkh[4], bkl[4];
                ldsm4(bkh, kh_s + ra);
                ldsm4(bkl, kl_s + ra);
                mma16816h(sc[2 * nb],     aqh, &bkh[0]);
                mma16816h(sc[2 * nb],     aqh, &bkl[0]);
                mma16816h(sc[2 * nb],     aql, &bkh[0]);
                mma16816h(sc[2 * nb + 1], aqh, &bkh[2]);
                mma16816h(sc[2 * nb + 1], aqh, &bkl[2]);
                mma16816h(sc[2 * nb + 1], aql, &bkh[2]);
            }
        }

        #pragma unroll
        for (int j = 0; j < 8; j++)
            #pragma unroll
            for (int c = 0; c < 4; c++) sc[j][c] *= SCL;
        if (kb == qb) {
            const int r0 = q0 + warp * 16 + (lane >> 2);
            #pragma unroll
            for (int j = 0; j < 8; j++)
                #pragma unroll
                for (int c = 0; c < 4; c++) {
                    const int col = kb * 64 + j * 8 + (lane & 3) * 2 + (c & 1);
                    const int row = r0 + (c >> 1) * 8;
                    if (col > row) sc[j][c] = -1e30f;
                }
        }

        float mx0 = -1e30f, mx1 = -1e30f;
        #pragma unroll
        for (int j = 0; j < 8; j++) {
            mx0 = fmaxf(mx0, fmaxf(sc[j][0], sc[j][1]));
            mx1 = fmaxf(mx1, fmaxf(sc[j][2], sc[j][3]));
        }
        mx0 = fmaxf(mx0, __shfl_xor_sync(0xffffffffu, mx0, 1));
        mx0 = fmaxf(mx0, __shfl_xor_sync(0xffffffffu, mx0, 2));
        mx1 = fmaxf(mx1, __shfl_xor_sync(0xffffffffu, mx1, 1));
        mx1 = fmaxf(mx1, __shfl_xor_sync(0xffffffffu, mx1, 2));
        const float mn0 = fmaxf(m0, mx0), mn1 = fmaxf(m1, mx1);
        const float a0  = exp2f(m0 - mn0);
        const float a1  = exp2f(m1 - mn1);
        m0 = mn0; m1 = mn1;

        float s0 = 0.0f, s1 = 0.0f;
        #pragma unroll
        for (int j = 0; j < 8; j++) {
            sc[j][0] = exp2f(sc[j][0] - mn0);
            sc[j][1] = exp2f(sc[j][1] - mn0);
            sc[j][2] = exp2f(sc[j][2] - mn1);
            sc[j][3] = exp2f(sc[j][3] - mn1);
            s0 += sc[j][0] + sc[j][1];
            s1 += sc[j][2] + sc[j][3];
        }
        lp0 = lp0 * a0 + s0;
        lp1 = lp1 * a1 + s1;
        #pragma unroll
        for (int j = 0; j < 8; j++) {
            o[j][0] *= a0; o[j][1] *= a0;
            o[j][2] *= a1; o[j][3] *= a1;
        }

        #pragma unroll
        for (int j = 0; j < 4; j++) {
            const int t0 = 2 * j, t1 = 2 * j + 1;
            uint32_t ph[4];
            ph[0] = packh2(sc[t0][0], sc[t0][1]);
            ph[1] = packh2(sc[t0][2], sc[t0][3]);
            ph[2] = packh2(sc[t1][0], sc[t1][1]);
            ph[3] = packh2(sc[t1][2], sc[t1][3]);
            #pragma unroll
            for (int nb = 0; nb < 4; nb++) {
                uint32_t ra = (uint32_t)(j * 16 + vrow) * (ASTR * 2) + vcol + nb * 32;
                uint32_t bvh[4], bvl[4];
                ldsm4t(bvh, vh_s + ra);
                ldsm4t(bvl, vl_s + ra);
                mma16816h(o[2 * nb],     ph, &bvh[0]);
                mma16816h(o[2 * nb],     ph, &bvl[0]);
                mma16816h(o[2 * nb + 1], ph, &bvh[2]);
                mma16816h(o[2 * nb + 1], ph, &bvl[2]);
            }
        }
        __syncthreads();
    }

    lp0 += __shfl_xor_sync(0xffffffffu, lp0, 1);
    lp0 += __shfl_xor_sync(0xffffffffu, lp0, 2);
    lp1 += __shfl_xor_sync(0xffffffffu, lp1, 1);
    lp1 += __shfl_xor_sync(0xffffffffu, lp1, 2);
    const float inv0 = 1.0f / lp0, inv1 = 1.0f / lp1;
    const int r  = q0 + warp * 16 + (lane >> 2);
    const int cb = h * 64 + (lane & 3) * 2;
    #pragma unroll
    for (int j = 0; j < 8; j++) {
        const int col = cb + j * 8;
        float f0 = o[j][0] * inv0, f1 = o[j][1] * inv0;
        float f2 = o[j][2] * inv1, f3 = o[j][3] * inv1;
        __half2 h0 = __float22half2_rn(make_float2(f0, f1));
        __half2 h1 = __float22half2_rn(make_float2(f2, f3));
        __half2 l0v = __float22half2_rn(make_float2(
            f0 - __half2float(h0.x), f1 - __half2float(h0.y)));
        __half2 l1v = __float22half2_rn(make_float2(
            f2 - __half2float(h1.x), f3 - __half2float(h1.y)));
        *(__half2*)&g_ah[(size_t)r * DM + col]       = h0;
        *(__half2*)&g_al[(size_t)r * DM + col]       = l0v;
        *(__half2*)&g_ah[(size_t)(r + 8) * DM + col] = h1;
        *(__half2*)&g_al[(size_t)(r + 8) * DM + col] = l1v;
    }
}

// ============================================================
// launch
// ============================================================
extern "C" void kernel_launch(void* const* d_in, const int* in_sizes, int n_in,
                              void* d_out, int out_size) {
    const float* x  = (const float*)d_in[0];
    const float* wq = (const float*)d_in[1];
    const float* wk = (const float*)d_in[2];
    const float* wv = (const float*)d_in[3];
    const float* wo = (const float*)d_in[4];
    float* out = (float*)d_out;

    __half *xh, *xl, *ah, *al;
    __half *wqh, *wql, *wkh, *wkl, *wvh, *wvl, *woh, *wol;
    __half *qh, *ql, *kh, *kl, *vh, *vl;
    cudaGetSymbolAddress((void**)&xh,  g_xh);
    cudaGetSymbolAddress((void**)&xl,  g_xl);
    cudaGetSymbolAddress((void**)&ah,  g_ah);
    cudaGetSymbolAddress((void**)&al,  g_al);
    cudaGetSymbolAddress((void**)&wqh, g_wqh);
    cudaGetSymbolAddress((void**)&wql, g_wql);
    cudaGetSymbolAddress((void**)&wkh, g_wkh);
    cudaGetSymbolAddress((void**)&wkl, g_wkl);
    cudaGetSymbolAddress((void**)&wvh, g_wvh);
    cudaGetSymbolAddress((void**)&wvl, g_wvl);
    cudaGetSymbolAddress((void**)&woh, g_woh);
    cudaGetSymbolAddress((void**)&wol, g_wol);
    cudaGetSymbolAddress((void**)&qh,  g_qh);
    cudaGetSymbolAddress((void**)&ql,  g_ql);
    cudaGetSymbolAddress((void**)&kh,  g_kh);
    cudaGetSymbolAddress((void**)&kl,  g_kl);
    cudaGetSymbolAddress((void**)&vh,  g_vh);
    cudaGetSymbolAddress((void**)&vl,  g_vl);

    cudaFuncSetAttribute(gemm_tc,
                         cudaFuncAttributeMaxDynamicSharedMemorySize, GEMM_SMEM);
    cudaFuncSetAttribute(attn_tc,
                         cudaFuncAttributeMaxDynamicSharedMemorySize, ATT_SMEM);

    const int nx4 = SEQ * DM / 4;
    const int nw4 = DM * DM / 4;

    rope_table_kernel<<<(SEQ * 32) / 256, 256>>>();
    conv_split<<<(nx4 + 255) / 256, 256>>>((const float4*)x,
                                           (__half2*)xh, (__half2*)xl, nx4);
    conv_split3<<<dim3((nw4 + 255) / 256, 3), 256>>>(
        (const float4*)wq, (const float4*)wk, (const float4*)wv,
        (__half2*)wqh, (__half2*)wql,
        (__half2*)wkh, (__half2*)wkl,
        (__half2*)wvh, (__half2*)wvl, nw4);
    conv_split<<<(nw4 + 255) / 256, 256>>>((const float4*)wo,
                                           (__half2*)woh, (__half2*)wol, nw4);

    // QKV: 24 N-tiles -> fp16 hi/lo head-major with fused RoPE
    gemm_tc<<<dim3(24, 32), 256, GEMM_SMEM>>>(xh, xl,
                                              wqh, wql, wkh, wkl, wvh, wvl,
                                              nullptr,
                                              qh, ql, kh, kl, vh, vl, 1);

    attn_tc<<<dim3(SEQ / 64, NH), 128, ATT_SMEM>>>();

    // Wo: fp32 out (2-term)
    gemm_tc<<<dim3(8, 32), 256, GEMM_SMEM>>>(ah, al,
                                             woh, wol, woh, wol, woh, wol,
                                             out,
                                             nullptr, nullptr, nullptr,
                                             nullptr, nullptr, nullptr, 0);
}

// round 17
// speedup vs baseline: 1.3761x; 1.1112x over previous
#include <cuda_runtime.h>
#include <cuda_bf16.h>
#include <cuda_fp16.h>
#include <math.h>
#include <cstdint>

#define SEQ   4096
#define DM    1024
#define NH    16
#define DK    64

// ---- fp16 hi/lo buffers (all tensor-core operands) ----
__device__ __half g_xh[SEQ * DM], g_xl[SEQ * DM];
__device__ __half g_ah[SEQ * DM], g_al[SEQ * DM];   // attention output
__device__ __half g_wqh[DM * DM], g_wql[DM * DM];
__device__ __half g_wkh[DM * DM], g_wkl[DM * DM];
__device__ __half g_wvh[DM * DM], g_wvl[DM * DM];
__device__ __half g_woh[DM * DM], g_wol[DM * DM];
// head-major [NH][SEQ][DK] Q/K hi/lo, V hi only (lo dropped: linear 2^-12 path)
__device__ __half g_qh[NH * SEQ * DK], g_ql[NH * SEQ * DK];
__device__ __half g_kh[NH * SEQ * DK], g_kl[NH * SEQ * DK];
__device__ __half g_vh[NH * SEQ * DK];

__device__ float g_rope_cos[SEQ * 32];
__device__ float g_rope_sin[SEQ * 32];

// ============================================================
// RoPE table (double trig, fp32 phase rounding like the reference)
// ============================================================
__global__ void rope_table_kernel() {
    int t = blockIdx.x * blockDim.x + threadIdx.x;
    int jj  = t & 31;
    int pos = t >> 5;
    if (pos >= SEQ) return;
    float invf = (float)pow(10000.0, -(double)jj / 32.0);
    float freq = (float)pos * invf;
    g_rope_cos[pos * 32 + jj] = (float)cos((double)freq);
    g_rope_sin[pos * 32 + jj] = (float)sin((double)freq);
}

// ============================================================
// fp32 -> (hi, lo) fp16 split (combined 22-bit mantissa)
// ============================================================
__device__ __forceinline__ void split4(const float4 v,
                                       __half2* hi, __half2* lo, int i) {
    __half2 a = __float22half2_rn(make_float2(v.x, v.y));
    __half2 b = __float22half2_rn(make_float2(v.z, v.w));
    __half2 c = __float22half2_rn(make_float2(v.x - __half2float(a.x),
                                              v.y - __half2float(a.y)));
    __half2 d = __float22half2_rn(make_float2(v.z - __half2float(b.x),
                                              v.w - __half2float(b.y)));
    hi[2 * i + 0] = a;
    hi[2 * i + 1] = b;
    lo[2 * i + 0] = c;
    lo[2 * i + 1] = d;
}

__global__ void conv_split(const float4* __restrict__ src,
                           __half2* __restrict__ hi,
                           __half2* __restrict__ lo, int n4) {
    int i = blockIdx.x * blockDim.x + threadIdx.x;
    if (i >= n4) return;
    split4(src[i], hi, lo, i);
}

__global__ void conv_split3(const float4* __restrict__ s0,
                            const float4* __restrict__ s1,
                            const float4* __restrict__ s2,
                            __half2* __restrict__ h0, __half2* __restrict__ l0,
                            __half2* __restrict__ h1, __half2* __restrict__ l1,
                            __half2* __restrict__ h2, __half2* __restrict__ l2,
                            int n4) {
    int i = blockIdx.x * blockDim.x + threadIdx.x;
    if (i >= n4) return;
    const float4* src = (blockIdx.y == 0) ? s0 : (blockIdx.y == 1) ? s1 : s2;
    __half2* hi       = (blockIdx.y == 0) ? h0 : (blockIdx.y == 1) ? h1 : h2;
    __half2* lo       = (blockIdx.y == 0) ? l0 : (blockIdx.y == 1) ? l1 : l2;
    split4(src[i], hi, lo, i);
}

// ============================================================
// warp-mma helpers (fp16 everywhere)
// ============================================================
__device__ __forceinline__ uint32_t s2u(const void* p) {
    uint32_t a;
    asm("{ .reg .u64 t; cvta.to.shared.u64 t, %1; cvt.u32.u64 %0, t; }"
        : "=r"(a) : "l"(p));
    return a;
}

__device__ __forceinline__ void mma16816h(float* d, const uint32_t* a,
                                          const uint32_t* b) {
    asm volatile(
        "mma.sync.aligned.m16n8k16.row.col.f32.f16.f16.f32 "
        "{%0,%1,%2,%3}, {%4,%5,%6,%7}, {%8,%9}, {%0,%1,%2,%3};"
        : "+f"(d[0]), "+f"(d[1]), "+f"(d[2]), "+f"(d[3])
        : "r"(a[0]), "r"(a[1]), "r"(a[2]), "r"(a[3]), "r"(b[0]), "r"(b[1]));
}

__device__ __forceinline__ void ldsm4(uint32_t* r, uint32_t addr) {
    asm volatile("ldmatrix.sync.aligned.m8n8.x4.shared.b16 {%0,%1,%2,%3}, [%4];"
                 : "=r"(r[0]), "=r"(r[1]), "=r"(r[2]), "=r"(r[3]) : "r"(addr));
}

__device__ __forceinline__ void ldsm4t(uint32_t* r, uint32_t addr) {
    asm volatile("ldmatrix.sync.aligned.m8n8.x4.trans.shared.b16 {%0,%1,%2,%3}, [%4];"
                 : "=r"(r[0]), "=r"(r[1]), "=r"(r[2]), "=r"(r[3]) : "r"(addr));
}

__device__ __forceinline__ void ldsm2(uint32_t* r, uint32_t addr) {
    asm volatile("ldmatrix.sync.aligned.m8n8.x2.shared.b16 {%0,%1}, [%2];"
                 : "=r"(r[0]), "=r"(r[1]) : "r"(addr));
}

__device__ __forceinline__ uint32_t packh2(float lo, float hi) {
    __half2 h = __float22half2_rn(make_float2(lo, hi));
    return *(uint32_t*)&h;
}

// ============================================================
// fp16 split GEMM via mma.sync:  D[m,n] = sum_k A[m,k] * B[n,k]
// 3 terms for Q/K (exponent path); 2 terms for V and Wo (linear).
// CTA 128x128, BK=32, 256 thr (8 warps, 64x32 warp tiles).
// mode 0: fp32 out (Wo). mode 1: QKV epilogue (RoPE + fp16 hi/lo;
// V writes hi only).
// ============================================================
#define KPAD      40
#define TILE_B    (128 * KPAD * 2)
#define STAGE_B   (4 * TILE_B)
#define GEMM_SMEM (2 * STAGE_B)

__device__ __forceinline__ void load_tile4(uint32_t st,
                                           const __half* ah, const __half* al,
                                           const __half* bh, const __half* bl,
                                           int tid, bool need_al) {
    #pragma unroll
    for (int i = 0; i < 2; i++) {
        int c   = tid + 256 * i;
        int row = c >> 2;
        int sg  = (c & 3) << 4;
        uint32_t soff = (uint32_t)row * (KPAD * 2) + (uint32_t)sg;
        size_t   goff = (size_t)row * (DM * 2) + sg;
        asm volatile("cp.async.cg.shared.global [%0], [%1], 16;"
                     :: "r"(st + 0 * TILE_B + soff), "l"((const char*)ah + goff) : "memory");
        if (need_al)
            asm volatile("cp.async.cg.shared.global [%0], [%1], 16;"
                         :: "r"(st + 1 * TILE_B + soff), "l"((const char*)al + goff) : "memory");
        asm volatile("cp.async.cg.shared.global [%0], [%1], 16;"
                     :: "r"(st + 2 * TILE_B + soff), "l"((const char*)bh + goff) : "memory");
        asm volatile("cp.async.cg.shared.global [%0], [%1], 16;"
                     :: "r"(st + 3 * TILE_B + soff), "l"((const char*)bl + goff) : "memory");
    }
}

__global__ void __launch_bounds__(256)
gemm_tc(const __half* __restrict__ Ah, const __half* __restrict__ Al,
        const __half* __restrict__ B0h, const __half* __restrict__ B0l,
        const __half* __restrict__ B1h, const __half* __restrict__ B1l,
        const __half* __restrict__ B2h, const __half* __restrict__ B2l,
        float* __restrict__ Dout,
        __half* __restrict__ Oqh, __half* __restrict__ Oql,
        __half* __restrict__ Okh, __half* __restrict__ Okl,
        __half* __restrict__ Ovh,
        int mode) {
    extern __shared__ char smraw[];
    const uint32_t sb = s2u(smraw);

    const int tid  = threadIdx.x;
    const int lane = tid & 31;
    const int wid  = tid >> 5;
    const int warp_m = (wid & 1) * 64;
    const int warp_n = (wid >> 1) * 32;

    const int ntile = blockIdx.x;
    const int which = ntile >> 3;
    const int nloc  = (ntile & 7) * 128;
    const int m0    = blockIdx.y * 128;

    const __half* Bh = (which == 0) ? B0h : (which == 1) ? B1h : B2h;
    const __half* Bl = (which == 0) ? B0l : (which == 1) ? B1l : B2l;

    // 3 terms only for Q/K projections (softmax-exponent-amplified path)
    const bool t3 = (mode == 1) && (which < 2);

    const __half* Abh = Ah + (size_t)m0 * DM;
    const __half* Abl = Al + (size_t)m0 * DM;
    const __half* Bbh = Bh + (size_t)nloc * DM;
    const __half* Bbl = Bl + (size_t)nloc * DM;

    float acc[4][4][4];
    #pragma unroll
    for (int i = 0; i < 4; i++)
        #pragma unroll
        for (int j = 0; j < 4; j++)
            #pragma unroll
            for (int r = 0; r < 4; r++) acc[i][j][r] = 0.0f;

    const uint32_t a_off = (uint32_t)(lane & 15) * (KPAD * 2) + (uint32_t)(lane >> 4) * 16;
    const int bl16 = lane & 15;
    const uint32_t b_off = (uint32_t)(bl16 & 7) * (KPAD * 2) + (uint32_t)(bl16 >> 3) * 16;

    load_tile4(sb, Abh, Abl, Bbh, Bbl, tid, t3);
    asm volatile("cp.async.commit_group;" ::: "memory");

    for (int kb = 0; kb < 32; kb++) {
        const uint32_t st = sb + (uint32_t)(kb & 1) * STAGE_B;
        if (kb + 1 < 32) {
            const int ko = (kb + 1) * 32;
            load_tile4(sb + (uint32_t)((kb + 1) & 1) * STAGE_B,
                       Abh + ko, Abl + ko, Bbh + ko, Bbl + ko, tid, t3);
            asm volatile("cp.async.commit_group;" ::: "memory");
            asm volatile("cp.async.wait_group 1;" ::: "memory");
        } else {
            asm volatile("cp.async.wait_group 0;" ::: "memory");
        }
        __syncthreads();

        #pragma unroll
        for (int ks = 0; ks < 2; ks++) {
            const uint32_t k0b = (uint32_t)ks * 32;
            uint32_t ahf[4][4], bhf[4][2], blf[4][2];
            #pragma unroll
            for (int mi = 0; mi < 4; mi++) {
                uint32_t ra = (uint32_t)(warp_m + mi * 16) * (KPAD * 2) + k0b + a_off;
                ldsm4(ahf[mi], st + 0 * TILE_B + ra);
            }
            #pragma unroll
            for (int ni = 0; ni < 4; ni++) {
                uint32_t rb = (uint32_t)(warp_n + ni * 8) * (KPAD * 2) + k0b + b_off;
                ldsm2(bhf[ni], st + 2 * TILE_B + rb);
                ldsm2(blf[ni], st + 3 * TILE_B + rb);
            }
            #pragma unroll
            for (int mi = 0; mi < 4; mi++)
                #pragma unroll
                for (int ni = 0; ni < 4; ni++) {
                    mma16816h(acc[mi][ni], ahf[mi], bhf[ni]);
                    mma16816h(acc[mi][ni], ahf[mi], blf[ni]);
                }
            if (t3) {
                uint32_t alf[4][4];
                #pragma unroll
                for (int mi = 0; mi < 4; mi++) {
                    uint32_t ra = (uint32_t)(warp_m + mi * 16) * (KPAD * 2) + k0b + a_off;
                    ldsm4(alf[mi], st + 1 * TILE_B + ra);
                }
                #pragma unroll
                for (int mi = 0; mi < 4; mi++)
                    #pragma unroll
                    for (int ni = 0; ni < 4; ni++)
                        mma16816h(acc[mi][ni], alf[mi], bhf[ni]);
            }
        }
        __syncthreads();
    }

    const int rope = (mode == 1) && (which < 2);
    __half* Wh = (which == 0) ? Oqh : (which == 1) ? Okh : Ovh;
    __half* Wl = (which == 0) ? Oql : (which == 1) ? Okl : nullptr;

    #pragma unroll
    for (int mi = 0; mi < 4; mi++) {
        #pragma unroll
        for (int ni = 0; ni < 4; ni++) {
            const int r0  = m0 + warp_m + mi * 16 + (lane >> 2);
            const int col = nloc + warp_n + ni * 8 + (lane & 3) * 2;
            float c0 = acc[mi][ni][0], c1 = acc[mi][ni][1];
            float c2 = acc[mi][ni][2], c3 = acc[mi][ni][3];
            if (rope) {
                const int jj = (col & (DK - 1)) >> 1;
                float cs = g_rope_cos[r0 * 32 + jj];
                float sn = g_rope_sin[r0 * 32 + jj];
                float e = c0, o = c1;
                c0 = cs * e - sn * o;
                c1 = sn * e + cs * o;
                cs = g_rope_cos[(r0 + 8) * 32 + jj];
                sn = g_rope_sin[(r0 + 8) * 32 + jj];
                e = c2; o = c3;
                c2 = cs * e - sn * o;
                c3 = sn * e + cs * o;
            }
            if (mode == 0) {
                *(float2*)&Dout[(size_t)r0 * DM + col]       = make_float2(c0, c1);
                *(float2*)&Dout[(size_t)(r0 + 8) * DM + col] = make_float2(c2, c3);
            } else {
                const int head = col >> 6;
                const int d    = col & 63;
                const size_t p0 = ((size_t)head * SEQ + r0) * DK + d;
                const size_t p1 = ((size_t)head * SEQ + r0 + 8) * DK + d;
                __half2 h0 = __float22half2_rn(make_float2(c0, c1));
                __half2 h1 = __float22half2_rn(make_float2(c2, c3));
                *(__half2*)&Wh[p0] = h0;
                *(__half2*)&Wh[p1] = h1;
                if (which < 2) {    // V needs hi only
                    __half2 l0 = __float22half2_rn(make_float2(
                        c0 - __half2float(h0.x), c1 - __half2float(h0.y)));
                    __half2 l1 = __float22half2_rn(make_float2(
                        c2 - __half2float(h1.x), c3 - __half2float(h1.y)));
                    *(__half2*)&Wl[p0] = l0;
                    *(__half2*)&Wl[p1] = l1;
                }
            }
        }
    }
}

// ============================================================
// Tensor-core causal flash attention (fp16).
// CTA = (head, 64-query block). 128 thr, 4 warps x 16 rows.
// QK^T: 3-term fp16 split. PV: single V (hi only) — 2^-12 linear.
// Stage = Kh,Kl,Vh (3 tiles); ATT_SMEM 73728 B -> 3 CTAs/SM.
// ============================================================
#define ASTR  72
#define ATILE (64 * ASTR * 2)
#define ATT_SMEM (8 * ATILE)     // Qh,Ql + 2 stages x (Kh,Kl,Vh)

__device__ __forceinline__ void aload(uint32_t dst, const __half* src, int tid) {
    const char* s = (const char*)src;
    #pragma unroll
    for (int i = 0; i < 4; i++) {
        int c   = tid + 128 * i;
        int row = c >> 3;
        int seg = (c & 7) << 4;
        asm volatile("cp.async.cg.shared.global [%0], [%1], 16;"
                     :: "r"(dst + (uint32_t)row * (ASTR * 2) + (uint32_t)seg),
                        "l"(s + (size_t)row * 128 + seg) : "memory");
    }
}

__global__ void __launch_bounds__(128) attn_tc() {
    extern __shared__ char smraw[];
    const uint32_t sb   = s2u(smraw);
    const uint32_t qh_s = sb;
    const uint32_t ql_s = sb + ATILE;
    const uint32_t kv0  = sb + 2 * ATILE;   // + stage*3*ATILE: Kh,Kl,Vh

    const int tid  = threadIdx.x;
    const int lane = tid & 31;
    const int warp = tid >> 5;
    const int h    = blockIdx.y;
    const int qb   = gridDim.x - 1 - blockIdx.x;
    const int q0   = qb * 64;

    const size_t hb = (size_t)h * SEQ * DK;

    aload(qh_s, g_qh + hb + (size_t)q0 * DK, tid);
    aload(ql_s, g_ql + hb + (size_t)q0 * DK, tid);
    aload(kv0 + 0 * ATILE, g_kh + hb, tid);
    aload(kv0 + 1 * ATILE, g_kl + hb, tid);
    aload(kv0 + 2 * ATILE, g_vh + hb, tid);
    asm volatile("cp.async.commit_group;" ::: "memory");

    float o[8][4];
    #pragma unroll
    for (int j = 0; j < 8; j++)
        #pragma unroll
        for (int c = 0; c < 4; c++) o[j][c] = 0.0f;
    float m0 = -1e30f, m1 = -1e30f;
    float lp0 = 0.0f, lp1 = 0.0f;

    const uint32_t qoff = (uint32_t)(warp * 16 + (lane & 15)) * (ASTR * 2)
                        + (uint32_t)(lane >> 4) * 16;
    const uint32_t krow = (uint32_t)((lane & 7) + ((lane >> 4) & 1) * 8);
    const uint32_t kcol = (uint32_t)((lane >> 3) & 1) * 16;
    const uint32_t vrow = (uint32_t)((lane & 7) + ((lane >> 3) & 1) * 8);
    const uint32_t vcol = (uint32_t)(lane >> 4) * 16;
    const float SCL = 0.125f * 1.44269504f;

    for (int kb = 0; kb <= qb; kb++) {
        if (kb < qb) {
            const uint32_t nst = kv0 + (uint32_t)((kb + 1) & 1) * (3 * ATILE);
            const size_t   gof = hb + (size_t)(kb + 1) * 64 * DK;
            aload(nst + 0 * ATILE, g_kh + gof, tid);
            aload(nst + 1 * ATILE, g_kl + gof, tid);
            aload(nst + 2 * ATILE, g_vh + gof, tid);
            asm volatile("cp.async.commit_group;" ::: "memory");
            asm volatile("cp.async.wait_group 1;" ::: "memory");
        } else {
            asm volatile("cp.async.wait_group 0;" ::: "memory");
        }
        __syncthreads();

        const uint32_t st   = kv0 + (uint32_t)(kb & 1) * (3 * ATILE);
        const uint32_t kh_s = st, kl_s = st + ATILE;
        const uint32_t vh_s = st + 2 * ATILE;

        float sc[8][4];
        #pragma unroll
        for (int j = 0; j < 8; j++)
            #pragma unroll
            for (int c = 0; c < 4; c++) sc[j][c] = 0.0f;

        #pragma unroll
        for (int ks = 0; ks < 4; ks++) {
            uint32_t aqh[4], aql[4];
            ldsm4(aqh, qh_s + qoff + ks * 32);
            ldsm4(aql, ql_s + qoff + ks * 32);
            #pragma unroll
            for (int nb = 0; nb < 4; nb++) {
                uint32_t ra = (uint32_t)(nb * 16 + krow) * (ASTR * 2) + kcol + ks * 32;
                uint32_t bkh[4], bkl[4];
                ldsm4(bkh, kh_s + ra);
                ldsm4(bkl, kl_s + ra);
                mma16816h(sc[2 * nb],     aqh, &bkh[0]);
                mma16816h(sc[2 * nb],     aqh, &bkl[0]);
                mma16816h(sc[2 * nb],     aql, &bkh[0]);
                mma16816h(sc[2 * nb + 1], aqh, &bkh[2]);
                mma16816h(sc[2 * nb + 1], aqh, &bkl[2]);
                mma16816h(sc[2 * nb + 1], aql, &bkh[2]);
            }
        }

        #pragma unroll
        for (int j = 0; j < 8; j++)
            #pragma unroll
            for (int c = 0; c < 4; c++) sc[j][c] *= SCL;
        if (kb == qb) {
            const int r0 = q0 + warp * 16 + (lane >> 2);
            #pragma unroll
            for (int j = 0; j < 8; j++)
                #pragma unroll
                for (int c = 0; c < 4; c++) {
                    const int col = kb * 64 + j * 8 + (lane & 3) * 2 + (c & 1);
                    const int row = r0 + (c >> 1) * 8;
                    if (col > row) sc[j][c] = -1e30f;
                }
        }

        float mx0 = -1e30f, mx1 = -1e30f;
        #pragma unroll
        for (int j = 0; j < 8; j++) {
            mx0 = fmaxf(mx0, fmaxf(sc[j][0], sc[j][1]));
            mx1 = fmaxf(mx1, fmaxf(sc[j][2], sc[j][3]));
        }
        mx0 = fmaxf(mx0, __shfl_xor_sync(0xffffffffu, mx0, 1));
        mx0 = fmaxf(mx0, __shfl_xor_sync(0xffffffffu, mx0, 2));
        mx1 = fmaxf(mx1, __shfl_xor_sync(0xffffffffu, mx1, 1));
        mx1 = fmaxf(mx1, __shfl_xor_sync(0xffffffffu, mx1, 2));
        const float mn0 = fmaxf(m0, mx0), mn1 = fmaxf(m1, mx1);
        const float a0  = exp2f(m0 - mn0);
        const float a1  = exp2f(m1 - mn1);
        m0 = mn0; m1 = mn1;

        float s0 = 0.0f, s1 = 0.0f;
        #pragma unroll
        for (int j = 0; j < 8; j++) {
            sc[j][0] = exp2f(sc[j][0] - mn0);
            sc[j][1] = exp2f(sc[j][1] - mn0);
            sc[j][2] = exp2f(sc[j][2] - mn1);
            sc[j][3] = exp2f(sc[j][3] - mn1);
            s0 += sc[j][0] + sc[j][1];
            s1 += sc[j][2] + sc[j][3];
        }
        lp0 = lp0 * a0 + s0;
        lp1 = lp1 * a1 + s1;
        #pragma unroll
        for (int j = 0; j < 8; j++) {
            o[j][0] *= a0; o[j][1] *= a0;
            o[j][2] *= a1; o[j][3] *= a1;
        }

        // ---- O += P Vh (single-V) ----
        #pragma unroll
        for (int j = 0; j < 4; j++) {
            const int t0 = 2 * j, t1 = 2 * j + 1;
            uint32_t ph[4];
            ph[0] = packh2(sc[t0][0], sc[t0][1]);
            ph[1] = packh2(sc[t0][2], sc[t0][3]);
            ph[2] = packh2(sc[t1][0], sc[t1][1]);
            ph[3] = packh2(sc[t1][2], sc[t1][3]);
            #pragma unroll
            for (int nb = 0; nb < 4; nb++) {
                uint32_t ra = (uint32_t)(j * 16 + vrow) * (ASTR * 2) + vcol + nb * 32;
                uint32_t bvh[4];
                ldsm4t(bvh, vh_s + ra);
                mma16816h(o[2 * nb],     ph, &bvh[0]);
                mma16816h(o[2 * nb + 1], ph, &bvh[2]);
            }
        }
        __syncthreads();
    }

    lp0 += __shfl_xor_sync(0xffffffffu, lp0, 1);
    lp0 += __shfl_xor_sync(0xffffffffu, lp0, 2);
    lp1 += __shfl_xor_sync(0xffffffffu, lp1, 1);
    lp1 += __shfl_xor_sync(0xffffffffu, lp1, 2);
    const float inv0 = 1.0f / lp0, inv1 = 1.0f / lp1;
    const int r  = q0 + warp * 16 + (lane >> 2);
    const int cb = h * 64 + (lane & 3) * 2;
    #pragma unroll
    for (int j = 0; j < 8; j++) {
        const int col = cb + j * 8;
        float f0 = o[j][0] * inv0, f1 = o[j][1] * inv0;
        float f2 = o[j][2] * inv1, f3 = o[j][3] * inv1;
        __half2 h0 = __float22half2_rn(make_float2(f0, f1));
        __half2 h1 = __float22half2_rn(make_float2(f2, f3));
        __half2 l0v = __float22half2_rn(make_float2(
            f0 - __half2float(h0.x), f1 - __half2float(h0.y)));
        __half2 l1v = __float22half2_rn(make_float2(
            f2 - __half2float(h1.x), f3 - __half2float(h1.y)));
        *(__half2*)&g_ah[(size_t)r * DM + col]       = h0;
        *(__half2*)&g_al[(size_t)r * DM + col]       = l0v;
        *(__half2*)&g_ah[(size_t)(r + 8) * DM + col] = h1;
        *(__half2*)&g_al[(size_t)(r + 8) * DM + col] = l1v;
    }
}

// ============================================================
// launch
// ============================================================
extern "C" void kernel_launch(void* const* d_in, const int* in_sizes, int n_in,
                              void* d_out, int out_size) {
    const float* x  = (const float*)d_in[0];
    const float* wq = (const float*)d_in[1];
    const float* wk = (const float*)d_in[2];
    const float* wv = (const float*)d_in[3];
    const float* wo = (const float*)d_in[4];
    float* out = (float*)d_out;

    __half *xh, *xl, *ah, *al;
    __half *wqh, *wql, *wkh, *wkl, *wvh, *wvl, *woh, *wol;
    __half *qh, *ql, *kh, *kl, *vh;
    cudaGetSymbolAddress((void**)&xh,  g_xh);
    cudaGetSymbolAddress((void**)&xl,  g_xl);
    cudaGetSymbolAddress((void**)&ah,  g_ah);
    cudaGetSymbolAddress((void**)&al,  g_al);
    cudaGetSymbolAddress((void**)&wqh, g_wqh);
    cudaGetSymbolAddress((void**)&wql, g_wql);
    cudaGetSymbolAddress((void**)&wkh, g_wkh);
    cudaGetSymbolAddress((void**)&wkl, g_wkl);
    cudaGetSymbolAddress((void**)&wvh, g_wvh);
    cudaGetSymbolAddress((void**)&wvl, g_wvl);
    cudaGetSymbolAddress((void**)&woh, g_woh);
    cudaGetSymbolAddress((void**)&wol, g_wol);
    cudaGetSymbolAddress((void**)&qh,  g_qh);
    cudaGetSymbolAddress((void**)&ql,  g_ql);
    cudaGetSymbolAddress((void**)&kh,  g_kh);
    cudaGetSymbolAddress((void**)&kl,  g_kl);
    cudaGetSymbolAddress((void**)&vh,  g_vh);

    cudaFuncSetAttribute(gemm_tc,
                         cudaFuncAttributeMaxDynamicSharedMemorySize, GEMM_SMEM);
    cudaFuncSetAttribute(attn_tc,
                         cudaFuncAttributeMaxDynamicSharedMemorySize, ATT_SMEM);

    const int nx4 = SEQ * DM / 4;
    const int nw4 = DM * DM / 4;

    rope_table_kernel<<<(SEQ * 32) / 256, 256>>>();
    conv_split<<<(nx4 + 255) / 256, 256>>>((const float4*)x,
                                           (__half2*)xh, (__half2*)xl, nx4);
    conv_split3<<<dim3((nw4 + 255) / 256, 3), 256>>>(
        (const float4*)wq, (const float4*)wk, (const float4*)wv,
        (__half2*)wqh, (__half2*)wql,
        (__half2*)wkh, (__half2*)wkl,
        (__half2*)wvh, (__half2*)wvl, nw4);
    conv_split<<<(nw4 + 255) / 256, 256>>>((const float4*)wo,
                                           (__half2*)woh, (__half2*)wol, nw4);

    // QKV: 24 N-tiles -> fp16 hi/lo head-major with fused RoPE (V: hi only)
    gemm_tc<<<dim3(24, 32), 256, GEMM_SMEM>>>(xh, xl,
                                              wqh, wql, wkh, wkl, wvh, wvl,
                                              nullptr,
                                              qh, ql, kh, kl, vh, 1);

    attn_tc<<<dim3(SEQ / 64, NH), 128, ATT_SMEM>>>();

    // Wo: fp32 out (2-term)
    gemm_tc<<<dim3(8, 32), 256, GEMM_SMEM>>>(ah, al,
                                             woh, wol, woh, wol, woh, wol,
                                             out,
                                             nullptr, nullptr, nullptr, nullptr,
                                             nullptr, 0);
}